// round 14
// baseline (speedup 1.0000x reference)
#include <cuda_runtime.h>
#include <cuda_bf16.h>
#include <cuda_fp8.h>
#include <cstdint>
#include <math_constants.h>

// Problem constants
#define BSZ 4
#define SEQ 1024
#define TOK (BSZ * SEQ)          // 4096
#define DMODEL 2048
#define NHEADS 32
#define NKV 8
#define HDIM 64
#define GROUPS (NHEADS / NKV)     // 4
#define KVDIM (NKV * HDIM)        // 512
#define QKVN (DMODEL + 2 * KVDIM) // 3072
#define ATTN_SCALE 0.125f
#define CORR_SCALE 4096.0f
#define CORR_INV   (1.0f / 4096.0f)

// ---------------- scratch (static device globals; no allocation) ----------
__device__ float g_QKV[(size_t)TOK * QKVN];
__device__ __align__(16) __nv_bfloat16 g_Ahi[(size_t)TOK * DMODEL];
__device__ __align__(16) __nv_bfloat16 g_Alo[(size_t)TOK * DMODEL];
__device__ __align__(16) __nv_bfloat16 g_Bhi[(size_t)QKVN * DMODEL]; // [N,K]
__device__ __align__(16) __nv_bfloat16 g_Blo[(size_t)QKVN * DMODEL];
__device__ __align__(16) __nv_bfloat16 g_Qh[(size_t)TOK * DMODEL];
__device__ __align__(16) __nv_bfloat16 g_Ql[(size_t)TOK * DMODEL];
__device__ __align__(16) __nv_bfloat16 g_Kh[(size_t)TOK * KVDIM];
__device__ __align__(16) __nv_bfloat16 g_Kl[(size_t)TOK * KVDIM];
__device__ __align__(16) __nv_bfloat16 g_Vh[(size_t)TOK * KVDIM];
__device__ __align__(16) __nv_bfloat16 g_Vl[(size_t)TOK * KVDIM];
// fp8 correction operands for the Wo GEMM
__device__ __align__(16) uint8_t g_Ah8[(size_t)TOK * DMODEL];
__device__ __align__(16) uint8_t g_Al8[(size_t)TOK * DMODEL];
__device__ __align__(16) uint8_t g_Bh8[(size_t)DMODEL * DMODEL];
__device__ __align__(16) uint8_t g_Bl8[(size_t)DMODEL * DMODEL];

// =================== PTX helpers (compute_103-safe) =========================
__device__ __forceinline__ uint32_t smem_u32(const void* p) {
    uint32_t a;
    asm("{ .reg .u64 t; cvta.to.shared.u64 t, %1; cvt.u32.u64 %0, t; }"
        : "=r"(a) : "l"(p));
    return a;
}

__device__ __forceinline__ uint8_t f2e4m3(float x) {
    __nv_fp8_e4m3 v(x);
    return *reinterpret_cast<uint8_t*>(&v);
}

#define CP_ASYNC16(dst, src) \
    asm volatile("cp.async.cg.shared.global [%0], [%1], 16;" \
                 :: "r"(dst), "l"(src) : "memory")
#define CP_COMMIT() asm volatile("cp.async.commit_group;" ::: "memory")
#define CP_WAIT2()  asm volatile("cp.async.wait_group 2;" ::: "memory")
#define CP_WAIT1()  asm volatile("cp.async.wait_group 1;" ::: "memory")
#define CP_WAIT0()  asm volatile("cp.async.wait_group 0;" ::: "memory")

#define LDMATRIX_X4(r0, r1, r2, r3, addr) \
    asm volatile("ldmatrix.sync.aligned.m8n8.x4.shared.b16 {%0,%1,%2,%3}, [%4];" \
                 : "=r"(r0), "=r"(r1), "=r"(r2), "=r"(r3) : "r"(addr))

#define LDMATRIX_X4T(r0, r1, r2, r3, addr) \
    asm volatile("ldmatrix.sync.aligned.m8n8.x4.trans.shared.b16 {%0,%1,%2,%3}, [%4];" \
                 : "=r"(r0), "=r"(r1), "=r"(r2), "=r"(r3) : "r"(addr))

#define MMA16816(d, a, b) \
    asm volatile("mma.sync.aligned.m16n8k16.row.col.f32.bf16.bf16.f32 " \
                 "{%0,%1,%2,%3}, {%4,%5,%6,%7}, {%8,%9}, {%0,%1,%2,%3};" \
                 : "+f"((d)[0]), "+f"((d)[1]), "+f"((d)[2]), "+f"((d)[3]) \
                 : "r"((a)[0]), "r"((a)[1]), "r"((a)[2]), "r"((a)[3]), \
                   "r"((b)[0]), "r"((b)[1]))

#define MMA_FP8(d, a, b) \
    asm volatile("mma.sync.aligned.m16n8k32.row.col.f32.e4m3.e4m3.f32 " \
                 "{%0,%1,%2,%3}, {%4,%5,%6,%7}, {%8,%9}, {%0,%1,%2,%3};" \
                 : "+f"((d)[0]), "+f"((d)[1]), "+f"((d)[2]), "+f"((d)[3]) \
                 : "r"((a)[0]), "r"((a)[1]), "r"((a)[2]), "r"((a)[3]), \
                   "r"((b)[0]), "r"((b)[1]))

// 128-byte rows, 8-chunk swizzle (bf16 tiles, flash)
__device__ __forceinline__ uint32_t swz8(int row, int c16) {
    return (uint32_t)(row * 128 + ((c16 ^ (row & 7)) * 16));
}
// 64-byte rows, 4-chunk swizzle (fp8 tiles)
__device__ __forceinline__ uint32_t swz4(int row, int c16) {
    return (uint32_t)(row * 64 + ((c16 ^ (row & 3)) * 16));
}

// =================== conversion kernels (verified R13) ======================
__global__ void split_kernel(const float* __restrict__ A,
                             __nv_bfloat162* __restrict__ H,
                             __nv_bfloat162* __restrict__ L, int n4)
{
    int i = blockIdx.x * blockDim.x + threadIdx.x;
    if (i >= n4) return;
    float4 v = reinterpret_cast<const float4*>(A)[i];
    __nv_bfloat16 h0 = __float2bfloat16(v.x);
    __nv_bfloat16 h1 = __float2bfloat16(v.y);
    __nv_bfloat16 h2 = __float2bfloat16(v.z);
    __nv_bfloat16 h3 = __float2bfloat16(v.w);
    __nv_bfloat16 l0 = __float2bfloat16(v.x - __bfloat162float(h0));
    __nv_bfloat16 l1 = __float2bfloat16(v.y - __bfloat162float(h1));
    __nv_bfloat16 l2 = __float2bfloat16(v.z - __bfloat162float(h2));
    __nv_bfloat16 l3 = __float2bfloat16(v.w - __bfloat162float(h3));
    H[2 * i]     = __nv_bfloat162(h0, h1);
    H[2 * i + 1] = __nv_bfloat162(h2, h3);
    L[2 * i]     = __nv_bfloat162(l0, l1);
    L[2 * i + 1] = __nv_bfloat162(l2, l3);
}

// merged Wq/Wk/Wv transpose+split in ONE launch (verified R13)
__global__ void transpose_split3(const float* __restrict__ Wq,
                                 const float* __restrict__ Wk,
                                 const float* __restrict__ Wv,
                                 __nv_bfloat16* __restrict__ Th,
                                 __nv_bfloat16* __restrict__ Tl)
{
    __shared__ float tile[32][33];
    int bx = blockIdx.x;
    const float* W;
    int N, rowoff;
    if (bx < 64)      { W = Wq; N = DMODEL; rowoff = 0; }
    else if (bx < 80) { W = Wk; N = KVDIM;  rowoff = DMODEL;        bx -= 64; }
    else              { W = Wv; N = KVDIM;  rowoff = DMODEL + KVDIM; bx -= 80; }

    int n = bx * 32 + threadIdx.x;
    int k = blockIdx.y * 32 + threadIdx.y;
#pragma unroll
    for (int j = 0; j < 32; j += 8)
        tile[threadIdx.y + j][threadIdx.x] = W[(size_t)(k + j) * N + n];
    __syncthreads();
    int k2 = blockIdx.y * 32 + threadIdx.x;
    int n2 = bx * 32 + threadIdx.y + rowoff;
#pragma unroll
    for (int j = 0; j < 32; j += 8) {
        float v = tile[threadIdx.x][threadIdx.y + j];
        __nv_bfloat16 h = __float2bfloat16(v);
        Th[(size_t)(n2 + j) * DMODEL + k2] = h;
        Tl[(size_t)(n2 + j) * DMODEL + k2] =
            __float2bfloat16(v - __bfloat162float(h));
    }
}

// Wo transpose: bf16 hi + fp8 hi + fp8 lo(x4096)
__global__ void transpose_split_fp8(const float* __restrict__ W,
                                    __nv_bfloat16* __restrict__ Th,
                                    uint8_t* __restrict__ T8h,
                                    uint8_t* __restrict__ T8l)
{
    __shared__ float tile[32][33];
    int n = blockIdx.x * 32 + threadIdx.x;
    int k = blockIdx.y * 32 + threadIdx.y;
#pragma unroll
    for (int j = 0; j < 32; j += 8)
        tile[threadIdx.y + j][threadIdx.x] = W[(size_t)(k + j) * DMODEL + n];
    __syncthreads();
    int k2 = blockIdx.y * 32 + threadIdx.x;
    int n2 = blockIdx.x * 32 + threadIdx.y;
#pragma unroll
    for (int j = 0; j < 32; j += 8) {
        float v = tile[threadIdx.x][threadIdx.y + j];
        __nv_bfloat16 h = __float2bfloat16(v);
        float hf = __bfloat162float(h);
        size_t o = (size_t)(n2 + j) * DMODEL + k2;
        Th[o]  = h;
        T8h[o] = f2e4m3(hf);
        T8l[o] = f2e4m3((v - hf) * CORR_SCALE);
    }
}

// merged QKV postprocess (verified R13)
#define QKVPP_TOTAL (TOK * 1408)
__global__ void qkv_post(const float* __restrict__ QKV,
                         const float* __restrict__ cs,
                         const float* __restrict__ sn,
                         __nv_bfloat16* __restrict__ Qh, __nv_bfloat16* __restrict__ Ql,
                         __nv_bfloat16* __restrict__ Kh, __nv_bfloat16* __restrict__ Kl,
                         __nv_bfloat162* __restrict__ Vh, __nv_bfloat162* __restrict__ Vl)
{
    int idx = blockIdx.x * blockDim.x + threadIdx.x;
    if (idx >= QKVPP_TOTAL) return;

    if (idx < TOK * 1024) {
        int i = idx & 31;
        int h = (idx >> 5) & 31;
        int t = idx >> 10;
        float c = cs[t * 32 + i];
        float s = sn[t * 32 + i];
        const float* in = QKV + (size_t)t * QKVN + h * HDIM;
        size_t ob = (size_t)t * DMODEL + h * HDIM;
        float x1 = in[i], x2 = in[i + 32];
        float y1 = (x1 * c - x2 * s) * ATTN_SCALE;
        float y2 = (x2 * c + x1 * s) * ATTN_SCALE;
        __nv_bfloat16 h1 = __float2bfloat16(y1);
        __nv_bfloat16 h2 = __float2bfloat16(y2);
        Qh[ob + i]      = h1;
        Qh[ob + i + 32] = h2;
        Ql[ob + i]      = __float2bfloat16(y1 - __bfloat162float(h1));
        Ql[ob + i + 32] = __float2bfloat16(y2 - __bfloat162float(h2));
    } else if (idx < TOK * 1280) {
        int r = idx - TOK * 1024;
        int i = r & 31;
        int h = (r >> 5) & 7;
        int t = r >> 8;
        float c = cs[t * 32 + i];
        float s = sn[t * 32 + i];
        const float* in = QKV + (size_t)t * QKVN + DMODEL + h * HDIM;
        size_t ob = (size_t)t * KVDIM + h * HDIM;
        float x1 = in[i], x2 = in[i + 32];
        float y1 = x1 * c - x2 * s;
        float y2 = x2 * c + x1 * s;
        __nv_bfloat16 h1 = __float2bfloat16(y1);
        __nv_bfloat16 h2 = __float2bfloat16(y2);
        Kh[ob + i]      = h1;
        Kh[ob + i + 32] = h2;
        Kl[ob + i]      = __float2bfloat16(y1 - __bfloat162float(h1));
        Kl[ob + i + 32] = __float2bfloat16(y2 - __bfloat162float(h2));
    } else {
        int r = idx - TOK * 1280;
        int c = r & 127;
        int t = r >> 7;
        float4 v = *reinterpret_cast<const float4*>(
            QKV + (size_t)t * QKVN + DMODEL + KVDIM + c * 4);
        __nv_bfloat16 h0 = __float2bfloat16(v.x);
        __nv_bfloat16 h1 = __float2bfloat16(v.y);
        __nv_bfloat16 h2 = __float2bfloat16(v.z);
        __nv_bfloat16 h3 = __float2bfloat16(v.w);
        size_t o = ((size_t)t * KVDIM + c * 4) / 2;
        Vh[o]     = __nv_bfloat162(h0, h1);
        Vh[o + 1] = __nv_bfloat162(h2, h3);
        Vl[o]     = __nv_bfloat162(__float2bfloat16(v.x - __bfloat162float(h0)),
                                   __float2bfloat16(v.y - __bfloat162float(h1)));
        Vl[o + 1] = __nv_bfloat162(__float2bfloat16(v.z - __bfloat162float(h2)),
                                   __float2bfloat16(v.w - __bfloat162float(h3)));
    }
}

// =================== HMMA GEMM (verified R8/R13, 3-term bf16) — QKV =========
#define BM 128
#define BN 128
#define BK 64
#define TILE_B (128 * BK * 2)          // 16384
#define STAGE_B (4 * TILE_B)           // 65536
#define GEMM_SMEM (3 * STAGE_B)        // 196608

__device__ __forceinline__ void stage_load(
    const __nv_bfloat16* __restrict__ aH, const __nv_bfloat16* __restrict__ aL,
    const __nv_bfloat16* __restrict__ bH, const __nv_bfloat16* __restrict__ bL,
    uint32_t sbase, int k0, int tid)
{
#pragma unroll
    for (int j = 0; j < 4; j++) {
        int i = tid + j * 256;
        int row = i >> 3;
        int c16 = i & 7;
        uint32_t doff = swz8(row, c16);
        size_t goff = (size_t)row * DMODEL + k0 + c16 * 8;
        CP_ASYNC16(sbase + 0 * TILE_B + doff, aH + goff);
        CP_ASYNC16(sbase + 1 * TILE_B + doff, aL + goff);
        CP_ASYNC16(sbase + 2 * TILE_B + doff, bH + goff);
        CP_ASYNC16(sbase + 3 * TILE_B + doff, bL + goff);
    }
}

__global__ void __launch_bounds__(256, 1) gemm_mma(
    const __nv_bfloat16* __restrict__ Ahi, const __nv_bfloat16* __restrict__ Alo,
    const __nv_bfloat16* __restrict__ Bhi, const __nv_bfloat16* __restrict__ Blo,
    float* __restrict__ C, int N)
{
    extern __shared__ char smem[];
    uint32_t sb = smem_u32(smem);
    const int tid = threadIdx.x;
    const int lane = tid & 31;
    const int wid = tid >> 5;
    const int wm = wid >> 2;
    const int wn = wid & 3;
    const int brow = blockIdx.y * BM;
    const int bcol = blockIdx.x * BN;

    const __nv_bfloat16* aH = Ahi + (size_t)brow * DMODEL;
    const __nv_bfloat16* aL = Alo + (size_t)brow * DMODEL;
    const __nv_bfloat16* bH = Bhi + (size_t)bcol * DMODEL;
    const __nv_bfloat16* bL = Blo + (size_t)bcol * DMODEL;

    float acc[4][4][4];
#pragma unroll
    for (int i = 0; i < 4; i++)
#pragma unroll
        for (int j = 0; j < 4; j++)
#pragma unroll
            for (int q = 0; q < 4; q++) acc[i][j][q] = 0.f;

    const int NC = DMODEL / BK;   // 32
#pragma unroll
    for (int s = 0; s < 3; s++) {
        stage_load(aH, aL, bH, bL, sb + s * STAGE_B, s * BK, tid);
        CP_COMMIT();
    }

    for (int c = 0; c < NC; c++) {
        if (c + 2 < NC)      CP_WAIT2();
        else if (c + 1 < NC) CP_WAIT1();
        else                 CP_WAIT0();
        __syncthreads();

        uint32_t st = sb + (uint32_t)(c % 3) * STAGE_B;

#pragma unroll
        for (int ks = 0; ks < 4; ks++) {
            uint32_t fAh[4][4], fAl[4][4];
#pragma unroll
            for (int mt = 0; mt < 4; mt++) {
                int row = wm * 64 + mt * 16 + (lane & 15);
                int c16 = ks * 2 + (lane >> 4);
                uint32_t off = swz8(row, c16);
                LDMATRIX_X4(fAh[mt][0], fAh[mt][1], fAh[mt][2], fAh[mt][3],
                            st + 0 * TILE_B + off);
                LDMATRIX_X4(fAl[mt][0], fAl[mt][1], fAl[mt][2], fAl[mt][3],
                            st + 1 * TILE_B + off);
            }
            uint32_t fBh[4][2], fBl[4][2];
#pragma unroll
            for (int pr = 0; pr < 2; pr++) {
                int nrel = wn * 32 + pr * 16 + ((lane >> 4) * 8 + (lane & 7));
                int c16 = ks * 2 + ((lane >> 3) & 1);
                uint32_t off = swz8(nrel, c16);
                LDMATRIX_X4(fBh[2 * pr][0], fBh[2 * pr][1],
                            fBh[2 * pr + 1][0], fBh[2 * pr + 1][1],
                            st + 2 * TILE_B + off);
                LDMATRIX_X4(fBl[2 * pr][0], fBl[2 * pr][1],
                            fBl[2 * pr + 1][0], fBl[2 * pr + 1][1],
                            st + 3 * TILE_B + off);
            }
#pragma unroll
            for (int mt = 0; mt < 4; mt++)
#pragma unroll
                for (int nt = 0; nt < 4; nt++) {
                    MMA16816(acc[mt][nt], fAh[mt], fBh[nt]);
                    MMA16816(acc[mt][nt], fAh[mt], fBl[nt]);
                    MMA16816(acc[mt][nt], fAl[mt], fBh[nt]);
                }
        }
        __syncthreads();
        if (c + 3 < NC) {
            stage_load(aH, aL, bH, bL, st, (c + 3) * BK, tid);
            CP_COMMIT();
        }
    }

#pragma unroll
    for (int mt = 0; mt < 4; mt++) {
#pragma unroll
        for (int nt = 0; nt < 4; nt++) {
            int m = brow + wm * 64 + mt * 16 + (lane >> 2);
            int n = bcol + wn * 32 + nt * 8 + (lane & 3) * 2;
            float2 v0 = make_float2(acc[mt][nt][0], acc[mt][nt][1]);
            float2 v1 = make_float2(acc[mt][nt][2], acc[mt][nt][3]);
            *reinterpret_cast<float2*>(C + (size_t)m * N + n) = v0;
            *reinterpret_cast<float2*>(C + (size_t)(m + 8) * N + n) = v1;
        }
    }
}

// =================== Wo GEMM: bf16 main + fp8 corrections ===================
// C = Ah.Bh (bf16)  +  (Ah8.Bl8' + Al8'.Bh8) / 4096   (fp8 e4m3, k32)
// Stage layout (64 KB): Ah bf16 16K | Bh bf16 16K | Ah8 8K | Al8 8K | Bh8 8K | Bl8 8K
#define WO_AH   0
#define WO_BH   16384
#define WO_A8H  32768
#define WO_A8L  40960
#define WO_B8H  49152
#define WO_B8L  57344
#define WO_STAGE 65536
#define WO_SMEM (3 * WO_STAGE)         // 196608

__device__ __forceinline__ void stage_load_wo(
    const __nv_bfloat16* __restrict__ aH, const __nv_bfloat16* __restrict__ bH,
    const uint8_t* __restrict__ a8h, const uint8_t* __restrict__ a8l,
    const uint8_t* __restrict__ b8h, const uint8_t* __restrict__ b8l,
    uint32_t sbase, int k0, int tid)
{
    // bf16 tiles: 128 rows x 128B, swz8
#pragma unroll
    for (int j = 0; j < 4; j++) {
        int i = tid + j * 256;
        int row = i >> 3;
        int c16 = i & 7;
        uint32_t doff = swz8(row, c16);
        size_t goff = (size_t)row * DMODEL + k0 + c16 * 8;
        CP_ASYNC16(sbase + WO_AH + doff, aH + goff);
        CP_ASYNC16(sbase + WO_BH + doff, bH + goff);
    }
    // fp8 tiles: 128 rows x 64B, swz4
#pragma unroll
    for (int j = 0; j < 2; j++) {
        int i = tid + j * 256;
        int row = i >> 2;
        int c16 = i & 3;
        uint32_t doff = swz4(row, c16);
        size_t goff = (size_t)row * DMODEL + k0 + c16 * 16;
        CP_ASYNC16(sbase + WO_A8H + doff, a8h + goff);
        CP_ASYNC16(sbase + WO_A8L + doff, a8l + goff);
        CP_ASYNC16(sbase + WO_B8H + doff, b8h + goff);
        CP_ASYNC16(sbase + WO_B8L + doff, b8l + goff);
    }
}

__global__ void __launch_bounds__(256, 1) gemm_wo(
    const __nv_bfloat16* __restrict__ Ahi,
    const uint8_t* __restrict__ Ah8, const uint8_t* __restrict__ Al8,
    const __nv_bfloat16* __restrict__ Bhi,
    const uint8_t* __restrict__ Bh8, const uint8_t* __restrict__ Bl8,
    float* __restrict__ C)
{
    extern __shared__ char smem[];
    uint32_t sb = smem_u32(smem);
    const int tid = threadIdx.x;
    const int lane = tid & 31;
    const int wid = tid >> 5;
    const int wm = wid >> 2;
    const int wn = wid & 3;
    const int brow = blockIdx.y * BM;
    const int bcol = blockIdx.x * BN;

    const __nv_bfloat16* aH = Ahi + (size_t)brow * DMODEL;
    const uint8_t* a8h = Ah8 + (size_t)brow * DMODEL;
    const uint8_t* a8l = Al8 + (size_t)brow * DMODEL;
    const __nv_bfloat16* bH = Bhi + (size_t)bcol * DMODEL;
    const uint8_t* b8h = Bh8 + (size_t)bcol * DMODEL;
    const uint8_t* b8l = Bl8 + (size_t)bcol * DMODEL;

    float accm[4][4][4], accc[4][4][4];
#pragma unroll
    for (int i = 0; i < 4; i++)
#pragma unroll
        for (int j = 0; j < 4; j++)
#pragma unroll
            for (int q = 0; q < 4; q++) { accm[i][j][q] = 0.f; accc[i][j][q] = 0.f; }

    const int NC = DMODEL / BK;   // 32
#pragma unroll
    for (int s = 0; s < 3; s++) {
        stage_load_wo(aH, bH, a8h, a8l, b8h, b8l, sb + s * WO_STAGE, s * BK, tid);
        CP_COMMIT();
    }

    for (int c = 0; c < NC; c++) {
        if (c + 2 < NC)      CP_WAIT2();
        else if (c + 1 < NC) CP_WAIT1();
        else                 CP_WAIT0();
        __syncthreads();

        uint32_t st = sb + (uint32_t)(c % 3) * WO_STAGE;

        // ---- main bf16 pass (hi x hi) ----
#pragma unroll
        for (int ks = 0; ks < 4; ks++) {
            uint32_t fA[4][4];
#pragma unroll
            for (int mt = 0; mt < 4; mt++) {
                int row = wm * 64 + mt * 16 + (lane & 15);
                int c16 = ks * 2 + (lane >> 4);
                LDMATRIX_X4(fA[mt][0], fA[mt][1], fA[mt][2], fA[mt][3],
                            st + WO_AH + swz8(row, c16));
            }
            uint32_t fB[4][2];
#pragma unroll
            for (int pr = 0; pr < 2; pr++) {
                int nrel = wn * 32 + pr * 16 + ((lane >> 4) * 8 + (lane & 7));
                int c16 = ks * 2 + ((lane >> 3) & 1);
                LDMATRIX_X4(fB[2 * pr][0], fB[2 * pr][1],
                            fB[2 * pr + 1][0], fB[2 * pr + 1][1],
                            st + WO_BH + swz8(nrel, c16));
            }
#pragma unroll
            for (int mt = 0; mt < 4; mt++)
#pragma unroll
                for (int nt = 0; nt < 4; nt++)
                    MMA16816(accm[mt][nt], fA[mt], fB[nt]);
        }

        // ---- fp8 correction pass (Ah8.Bl8 + Al8.Bh8), k32 steps ----
#pragma unroll
        for (int ks8 = 0; ks8 < 2; ks8++) {
            uint32_t a8H[4][4], a8L[4][4];
#pragma unroll
            for (int mt = 0; mt < 4; mt++) {
                int row = wm * 64 + mt * 16 + (lane & 15);
                int c16 = ks8 * 2 + (lane >> 4);
                uint32_t off = swz4(row, c16);
                LDMATRIX_X4(a8H[mt][0], a8H[mt][1], a8H[mt][2], a8H[mt][3],
                            st + WO_A8H + off);
                LDMATRIX_X4(a8L[mt][0], a8L[mt][1], a8L[mt][2], a8L[mt][3],
                            st + WO_A8L + off);
            }
            uint32_t b8H[4][2], b8L[4][2];
#pragma unroll
            for (int pr = 0; pr < 2; pr++) {
                int nrel = wn * 32 + pr * 16 + ((lane >> 4) * 8 + (lane & 7));
                int c16 = ks8 * 2 + ((lane >> 3) & 1);
                uint32_t off = swz4(nrel, c16);
                LDMATRIX_X4(b8H[2 * pr][0], b8H[2 * pr][1],
                            b8H[2 * pr + 1][0], b8H[2 * pr + 1][1],
                            st + WO_B8H + off);
                LDMATRIX_X4(b8L[2 * pr][0], b8L[2 * pr][1],
                            b8L[2 * pr + 1][0], b8L[2 * pr + 1][1],
                            st + WO_B8L + off);
            }
#pragma unroll
            for (int mt = 0; mt < 4; mt++)
#pragma unroll
                for (int nt = 0; nt < 4; nt++) {
                    MMA_FP8(accc[mt][nt], a8H[mt], b8L[nt]);
                    MMA_FP8(accc[mt][nt], a8L[mt], b8H[nt]);
                }
        }

        __syncthreads();
        if (c + 3 < NC) {
            stage_load_wo(aH, bH, a8h, a8l, b8h, b8l, st, (c + 3) * BK, tid);
            CP_COMMIT();
        }
    }

#pragma unroll
    for (int mt = 0; mt < 4; mt++) {
#pragma unroll
        for (int nt = 0; nt < 4; nt++) {
            int m = brow + wm * 64 + mt * 16 + (lane >> 2);
            int n = bcol + wn * 32 + nt * 8 + (lane & 3) * 2;
            float2 v0 = make_float2(accm[mt][nt][0] + accc[mt][nt][0] * CORR_INV,
                                    accm[mt][nt][1] + accc[mt][nt][1] * CORR_INV);
            float2 v1 = make_float2(accm[mt][nt][2] + accc[mt][nt][2] * CORR_INV,
                                    accm[mt][nt][3] + accc[mt][nt][3] * CORR_INV);
            *reinterpret_cast<float2*>(C + (size_t)m * DMODEL + n) = v0;
            *reinterpret_cast<float2*>(C + (size_t)(m + 8) * DMODEL + n) = v1;
        }
    }
}

// =================== tensor-core flash attention (verified R13 mainloop) ====
#define FQ_SMEM 32768
#define KV_BUF  32768
#define FLASH_SMEM (FQ_SMEM + 2 * KV_BUF)

__device__ __forceinline__ void stage_kv(
    const __nv_bfloat16* __restrict__ Kh, const __nv_bfloat16* __restrict__ Kl,
    const __nv_bfloat16* __restrict__ Vh, const __nv_bfloat16* __restrict__ Vl,
    uint32_t sbase, size_t gbase, int tid)
{
#pragma unroll
    for (int t = 0; t < 4; t++) {
        int i = tid + t * 128;
        int row = i >> 3;
        int c16 = i & 7;
        uint32_t doff = swz8(row, c16);
        size_t goff = gbase + (size_t)row * KVDIM + c16 * 8;
        CP_ASYNC16(sbase + 0     + doff, Kh + goff);
        CP_ASYNC16(sbase + 8192  + doff, Kl + goff);
        CP_ASYNC16(sbase + 16384 + doff, Vh + goff);
        CP_ASYNC16(sbase + 24576 + doff, Vl + goff);
    }
}

__global__ void __launch_bounds__(128) flash_mma(
    const __nv_bfloat16* __restrict__ Qh, const __nv_bfloat16* __restrict__ Ql,
    const __nv_bfloat16* __restrict__ Kh, const __nv_bfloat16* __restrict__ Kl,
    const __nv_bfloat16* __restrict__ Vh, const __nv_bfloat16* __restrict__ Vl,
    __nv_bfloat16* __restrict__ Oh, uint8_t* __restrict__ O8h,
    uint8_t* __restrict__ O8l)
{
    extern __shared__ char smem[];
    uint32_t sb = smem_u32(smem);
    const int qt = (int)gridDim.x - 1 - (int)blockIdx.x;   // LPT
    const int h  = blockIdx.y;
    const int b  = blockIdx.z;
    const int kvh = h / GROUPS;
    const int tid = threadIdx.x;
    const int lane = tid & 31;
    const int w = tid >> 5;
    const int qbase = qt * 128;

#pragma unroll
    for (int t = 0; t < 8; t++) {
        int i = tid + t * 128;
        int row = i >> 3;
        int c16 = i & 7;
        uint32_t doff = swz8(row, c16);
        size_t goff = (size_t)(b * SEQ + qbase + row) * DMODEL + h * HDIM + c16 * 8;
        CP_ASYNC16(sb + doff, Qh + goff);
        CP_ASYNC16(sb + 16384 + doff, Ql + goff);
    }
    size_t kvg0 = (size_t)(b * SEQ) * KVDIM + kvh * HDIM;
    stage_kv(Kh, Kl, Vh, Vl, sb + FQ_SMEM, kvg0, tid);
    CP_COMMIT();

    float acc[2][8][4];
#pragma unroll
    for (int mt = 0; mt < 2; mt++)
#pragma unroll
        for (int nt = 0; nt < 8; nt++)
#pragma unroll
            for (int e = 0; e < 4; e++) acc[mt][nt][e] = 0.f;
    float mrow[2][2] = {{-CUDART_INF_F, -CUDART_INF_F},
                        {-CUDART_INF_F, -CUDART_INF_F}};
    float lrow[2][2] = {{0.f, 0.f}, {0.f, 0.f}};

    const int nb = 2 * qt + 2;
    for (int c = 0; c < nb; c++) {
        if (c + 1 < nb) {
            stage_kv(Kh, Kl, Vh, Vl, sb + FQ_SMEM + ((c + 1) & 1) * KV_BUF,
                     kvg0 + (size_t)(c + 1) * 64 * KVDIM, tid);
            CP_COMMIT();
            CP_WAIT1();
        } else {
            CP_WAIT0();
        }
        __syncthreads();

        uint32_t sk = sb + FQ_SMEM + (c & 1) * KV_BUF;

        float S[2][8][4];
#pragma unroll
        for (int mt = 0; mt < 2; mt++)
#pragma unroll
            for (int nt = 0; nt < 8; nt++)
#pragma unroll
                for (int e = 0; e < 4; e++) S[mt][nt][e] = 0.f;

#pragma unroll
        for (int ks = 0; ks < 4; ks++) {
            uint32_t qh[2][4], ql[2][4];
#pragma unroll
            for (int mt = 0; mt < 2; mt++) {
                int row = w * 32 + mt * 16 + (lane & 15);
                int c16 = ks * 2 + (lane >> 4);
                uint32_t off = swz8(row, c16);
                LDMATRIX_X4(qh[mt][0], qh[mt][1], qh[mt][2], qh[mt][3], sb + off);
                LDMATRIX_X4(ql[mt][0], ql[mt][1], ql[mt][2], ql[mt][3],
                            sb + 16384 + off);
            }
#pragma unroll
            for (int np = 0; np < 4; np++) {
                int row = np * 16 + ((lane >> 4) * 8) + (lane & 7);
                int c16 = ks * 2 + ((lane >> 3) & 1);
                uint32_t off = swz8(row, c16);
                uint32_t kh[4], kl[4];
                LDMATRIX_X4(kh[0], kh[1], kh[2], kh[3], sk + off);
                LDMATRIX_X4(kl[0], kl[1], kl[2], kl[3], sk + 8192 + off);
#pragma unroll
                for (int mt = 0; mt < 2; mt++) {
                    MMA16816(S[mt][2 * np],     qh[mt], (kh + 0));
                    MMA16816(S[mt][2 * np + 1], qh[mt], (kh + 2));
                    MMA16816(S[mt][2 * np],     qh[mt], (kl + 0));
                    MMA16816(S[mt][2 * np + 1], qh[mt], (kl + 2));
                    MMA16816(S[mt][2 * np],     ql[mt], (kh + 0));
                    MMA16816(S[mt][2 * np + 1], ql[mt], (kh + 2));
                }
            }
        }

        if (c >= 2 * qt) {
            int kb = c * 64;
#pragma unroll
            for (int mt = 0; mt < 2; mt++) {
                int r0 = qbase + w * 32 + mt * 16 + (lane >> 2);
#pragma unroll
                for (int nt = 0; nt < 8; nt++) {
                    int key = kb + nt * 8 + (lane & 3) * 2;
                    if (key > r0)     S[mt][nt][0] = -CUDART_INF_F;
                    if (key + 1 > r0) S[mt][nt][1] = -CUDART_INF_F;
                    if (key > r0 + 8)     S[mt][nt][2] = -CUDART_INF_F;
                    if (key + 1 > r0 + 8) S[mt][nt][3] = -CUDART_INF_F;
                }
            }
        }

        uint32_t aPh[2][4][4], aPl[2][4][4];
#pragma unroll
        for (int mt = 0; mt < 2; mt++) {
#pragma unroll
            for (int e2 = 0; e2 < 2; e2++) {
                float mx = -CUDART_INF_F;
#pragma unroll
                for (int nt = 0; nt < 8; nt++)
                    mx = fmaxf(mx, fmaxf(S[mt][nt][2 * e2], S[mt][nt][2 * e2 + 1]));
                mx = fmaxf(mx, __shfl_xor_sync(0xffffffffu, mx, 1));
                mx = fmaxf(mx, __shfl_xor_sync(0xffffffffu, mx, 2));
                float mn = fmaxf(mrow[mt][e2], mx);
                float alpha = __expf(mrow[mt][e2] - mn);
                mrow[mt][e2] = mn;
                float sum = 0.f;
#pragma unroll
                for (int nt = 0; nt < 8; nt++) {
                    float p0 = __expf(S[mt][nt][2 * e2] - mn);
                    float p1 = __expf(S[mt][nt][2 * e2 + 1] - mn);
                    S[mt][nt][2 * e2] = p0;
                    S[mt][nt][2 * e2 + 1] = p1;
                    sum += p0 + p1;
                }
                sum += __shfl_xor_sync(0xffffffffu, sum, 1);
                sum += __shfl_xor_sync(0xffffffffu, sum, 2);
                lrow[mt][e2] = lrow[mt][e2] * alpha + sum;
#pragma unroll
                for (int nt = 0; nt < 8; nt++) {
                    acc[mt][nt][2 * e2] *= alpha;
                    acc[mt][nt][2 * e2 + 1] *= alpha;
                }
            }
#pragma unroll
            for (int kc = 0; kc < 4; kc++) {
#pragma unroll
                for (int r = 0; r < 4; r++) {
                    int nt = 2 * kc + (r >> 1);
                    int e0 = (r & 1) * 2;
                    float p0 = S[mt][nt][e0], p1 = S[mt][nt][e0 + 1];
                    __nv_bfloat162 hh = __floats2bfloat162_rn(p0, p1);
                    float r0 = p0 - __bfloat162float(hh.x);
                    float r1 = p1 - __bfloat162float(hh.y);
                    __nv_bfloat162 ll = __floats2bfloat162_rn(r0, r1);
                    aPh[mt][kc][r] = *reinterpret_cast<uint32_t*>(&hh);
                    aPl[mt][kc][r] = *reinterpret_cast<uint32_t*>(&ll);
                }
            }
        }

#pragma unroll
        for (int kc = 0; kc < 4; kc++) {
#pragma unroll
            for (int dp = 0; dp < 4; dp++) {
                int row = kc * 16 + ((lane >> 3) & 1) * 8 + (lane & 7);
                int c16 = dp * 2 + (lane >> 4);
                uint32_t off = swz8(row, c16);
                uint32_t vh[4], vl[4];
                LDMATRIX_X4T(vh[0], vh[1], vh[2], vh[3], sk + 16384 + off);
                LDMATRIX_X4T(vl[0], vl[1], vl[2], vl[3], sk + 24576 + off);
#pragma unroll
                for (int mt = 0; mt < 2; mt++) {
                    MMA16816(acc[mt][2 * dp],     aPh[mt][kc], (vh + 0));
                    MMA16816(acc[mt][2 * dp + 1], aPh[mt][kc], (vh + 2));
                    MMA16816(acc[mt][2 * dp],     aPh[mt][kc], (vl + 0));
                    MMA16816(acc[mt][2 * dp + 1], aPh[mt][kc], (vl + 2));
                    MMA16816(acc[mt][2 * dp],     aPl[mt][kc], (vh + 0));
                    MMA16816(acc[mt][2 * dp + 1], aPl[mt][kc], (vh + 2));
                }
            }
        }
        __syncthreads();
    }

    // epilogue: bf16 hi (main) + fp8 hi + fp8 lo(x4096) for the Wo GEMM
#pragma unroll
    for (int mt = 0; mt < 2; mt++) {
        float inv0 = 1.0f / lrow[mt][0];
        float inv1 = 1.0f / lrow[mt][1];
        int r0 = qbase + w * 32 + mt * 16 + (lane >> 2);
        size_t t0 = (size_t)(b * SEQ + r0) * DMODEL + h * HDIM;
        size_t t1 = t0 + 8 * DMODEL;
#pragma unroll
        for (int nt = 0; nt < 8; nt++) {
            int d = nt * 8 + (lane & 3) * 2;
            float v0 = acc[mt][nt][0] * inv0, v1 = acc[mt][nt][1] * inv0;
            float v2 = acc[mt][nt][2] * inv1, v3 = acc[mt][nt][3] * inv1;
            __nv_bfloat162 h01 = __floats2bfloat162_rn(v0, v1);
            __nv_bfloat162 h23 = __floats2bfloat162_rn(v2, v3);
            *reinterpret_cast<__nv_bfloat162*>(Oh + t0 + d) = h01;
            *reinterpret_cast<__nv_bfloat162*>(Oh + t1 + d) = h23;
            // fp8 hi (of the bf16 hi values)
            uint16_t p8h0 = (uint16_t)f2e4m3(__bfloat162float(h01.x)) |
                            ((uint16_t)f2e4m3(__bfloat162float(h01.y)) << 8);
            uint16_t p8h1 = (uint16_t)f2e4m3(__bfloat162float(h23.x)) |
                            ((uint16_t)f2e4m3(__bfloat162float(h23.y)) << 8);
            *reinterpret_cast<uint16_t*>(O8h + t0 + d) = p8h0;
            *reinterpret_cast<uint16_t*>(O8h + t1 + d) = p8h1;
            // fp8 lo (residual x4096)
            uint16_t p8l0 = (uint16_t)f2e4m3((v0 - __bfloat162float(h01.x)) * CORR_SCALE) |
                            ((uint16_t)f2e4m3((v1 - __bfloat162float(h01.y)) * CORR_SCALE) << 8);
            uint16_t p8l1 = (uint16_t)f2e4m3((v2 - __bfloat162float(h23.x)) * CORR_SCALE) |
                            ((uint16_t)f2e4m3((v3 - __bfloat162float(h23.y)) * CORR_SCALE) << 8);
            *reinterpret_cast<uint16_t*>(O8l + t0 + d) = p8l0;
            *reinterpret_cast<uint16_t*>(O8l + t1 + d) = p8l1;
        }
    }
}

// ---------------- launch ----------------------------------------------------
extern "C" void kernel_launch(void* const* d_in, const int* in_sizes, int n_in,
                              void* d_out, int out_size)
{
    const float* hidden = (const float*)d_in[0];
    const float* cs     = (const float*)d_in[1];
    const float* sn     = (const float*)d_in[2];
    const float* Wq     = (const float*)d_in[3];
    const float* Wk     = (const float*)d_in[4];
    const float* Wv     = (const float*)d_in[5];
    const float* Wo     = (const float*)d_in[6];
    float* out          = (float*)d_out;

    float* QKV = nullptr; cudaGetSymbolAddress((void**)&QKV, g_QKV);
    __nv_bfloat16* Ah = nullptr; cudaGetSymbolAddress((void**)&Ah, g_Ahi);
    __nv_bfloat16* Al = nullptr; cudaGetSymbolAddress((void**)&Al, g_Alo);
    __nv_bfloat16* Bh = nullptr; cudaGetSymbolAddress((void**)&Bh, g_Bhi);
    __nv_bfloat16* Bl = nullptr; cudaGetSymbolAddress((void**)&Bl, g_Blo);
    __nv_bfloat16* Qh = nullptr; cudaGetSymbolAddress((void**)&Qh, g_Qh);
    __nv_bfloat16* Ql = nullptr; cudaGetSymbolAddress((void**)&Ql, g_Ql);
    __nv_bfloat16* Kh = nullptr; cudaGetSymbolAddress((void**)&Kh, g_Kh);
    __nv_bfloat16* Kl = nullptr; cudaGetSymbolAddress((void**)&Kl, g_Kl);
    __nv_bfloat16* Vh = nullptr; cudaGetSymbolAddress((void**)&Vh, g_Vh);
    __nv_bfloat16* Vl = nullptr; cudaGetSymbolAddress((void**)&Vl, g_Vl);
    uint8_t* Ah8 = nullptr; cudaGetSymbolAddress((void**)&Ah8, g_Ah8);
    uint8_t* Al8 = nullptr; cudaGetSymbolAddress((void**)&Al8, g_Al8);
    uint8_t* Bh8 = nullptr; cudaGetSymbolAddress((void**)&Bh8, g_Bh8);
    uint8_t* Bl8 = nullptr; cudaGetSymbolAddress((void**)&Bl8, g_Bl8);

    static bool attr_set = false;
    if (!attr_set) {
        cudaFuncSetAttribute(gemm_mma, cudaFuncAttributeMaxDynamicSharedMemorySize,
                             GEMM_SMEM);
        cudaFuncSetAttribute(gemm_wo, cudaFuncAttributeMaxDynamicSharedMemorySize,
                             WO_SMEM);
        cudaFuncSetAttribute(flash_mma, cudaFuncAttributeMaxDynamicSharedMemorySize,
                             FLASH_SMEM);
        attr_set = true;
    }

    const int n4 = TOK * DMODEL / 4;

    // hidden -> bf16 hi/lo (A operand)
    split_kernel<<<n4 / 256, 256>>>(hidden, (__nv_bfloat162*)Ah,
                                    (__nv_bfloat162*)Al, n4);

    // B = [WqT ; WkT ; WvT] in ONE launch
    transpose_split3<<<dim3(96, DMODEL / 32), dim3(32, 8)>>>(Wq, Wk, Wv, Bh, Bl);

    // fused QKV GEMM (verified 3-term bf16)
    gemm_mma<<<dim3(QKVN / BN, TOK / BM), 256, GEMM_SMEM>>>(Ah, Al, Bh, Bl, QKV, QKVN);

    // merged postprocess: Q rope + K rope + V split, ONE launch
    qkv_post<<<(QKVPP_TOTAL + 255) / 256, 256>>>(QKV, cs, sn, Qh, Ql, Kh, Kl,
                                                 (__nv_bfloat162*)Vh,
                                                 (__nv_bfloat162*)Vl);

    // Wo transpose -> bf16 hi + fp8 hi/lo (Bh free after QKV GEMM)
    transpose_split_fp8<<<dim3(DMODEL / 32, DMODEL / 32), dim3(32, 8)>>>(
        Wo, Bh, Bh8, Bl8);

    // flash attention (LPT) -> writes bf16 hi + fp8 hi/lo A operands
    {
        dim3 grid(SEQ / 128, NHEADS, BSZ);
        flash_mma<<<grid, 128, FLASH_SMEM>>>(Qh, Ql, Kh, Kl, Vh, Vl, Ah, Ah8, Al8);
    }

    // out = attn @ Wo  (bf16 main + fp8 corrections)
    gemm_wo<<<dim3(DMODEL / BN, TOK / BM), 256, WO_SMEM>>>(
        Ah, Ah8, Al8, Bh, Bh8, Bl8, out);
}

// round 15
// speedup vs baseline: 1.1317x; 1.1317x over previous
#include <cuda_runtime.h>
#include <cuda_bf16.h>
#include <cstdint>
#include <math_constants.h>

// Problem constants
#define BSZ 4
#define SEQ 1024
#define TOK (BSZ * SEQ)          // 4096
#define DMODEL 2048
#define NHEADS 32
#define NKV 8
#define HDIM 64
#define GROUPS (NHEADS / NKV)     // 4
#define KVDIM (NKV * HDIM)        // 512
#define QKVN (DMODEL + 2 * KVDIM) // 3072
#define ATTN_SCALE 0.125f

// ---------------- scratch (static device globals; no allocation) ----------
__device__ float g_QKV[(size_t)TOK * QKVN];
__device__ __align__(16) __nv_bfloat16 g_Ahi[(size_t)TOK * DMODEL];
__device__ __align__(16) __nv_bfloat16 g_Alo[(size_t)TOK * DMODEL];
__device__ __align__(16) __nv_bfloat16 g_Bhi[(size_t)QKVN * DMODEL]; // [N,K]
__device__ __align__(16) __nv_bfloat16 g_Blo[(size_t)QKVN * DMODEL];
__device__ __align__(16) __nv_bfloat16 g_Qh[(size_t)TOK * DMODEL];
__device__ __align__(16) __nv_bfloat16 g_Ql[(size_t)TOK * DMODEL];
__device__ __align__(16) __nv_bfloat16 g_Kh[(size_t)TOK * KVDIM];
__device__ __align__(16) __nv_bfloat16 g_Kl[(size_t)TOK * KVDIM];
__device__ __align__(16) __nv_bfloat16 g_Vh[(size_t)TOK * KVDIM];
__device__ __align__(16) __nv_bfloat16 g_Vl[(size_t)TOK * KVDIM];

// =================== PTX helpers (compute_103-safe) =========================
__device__ __forceinline__ uint32_t smem_u32(const void* p) {
    uint32_t a;
    asm("{ .reg .u64 t; cvta.to.shared.u64 t, %1; cvt.u32.u64 %0, t; }"
        : "=r"(a) : "l"(p));
    return a;
}

#define CP_ASYNC16(dst, src) \
    asm volatile("cp.async.cg.shared.global [%0], [%1], 16;" \
                 :: "r"(dst), "l"(src) : "memory")
#define CP_COMMIT() asm volatile("cp.async.commit_group;" ::: "memory")
#define CP_WAIT2()  asm volatile("cp.async.wait_group 2;" ::: "memory")
#define CP_WAIT1()  asm volatile("cp.async.wait_group 1;" ::: "memory")
#define CP_WAIT0()  asm volatile("cp.async.wait_group 0;" ::: "memory")

#define LDMATRIX_X4(r0, r1, r2, r3, addr) \
    asm volatile("ldmatrix.sync.aligned.m8n8.x4.shared.b16 {%0,%1,%2,%3}, [%4];" \
                 : "=r"(r0), "=r"(r1), "=r"(r2), "=r"(r3) : "r"(addr))

#define LDMATRIX_X4T(r0, r1, r2, r3, addr) \
    asm volatile("ldmatrix.sync.aligned.m8n8.x4.trans.shared.b16 {%0,%1,%2,%3}, [%4];" \
                 : "=r"(r0), "=r"(r1), "=r"(r2), "=r"(r3) : "r"(addr))

#define MMA16816(d, a, b) \
    asm volatile("mma.sync.aligned.m16n8k16.row.col.f32.bf16.bf16.f32 " \
                 "{%0,%1,%2,%3}, {%4,%5,%6,%7}, {%8,%9}, {%0,%1,%2,%3};" \
                 : "+f"((d)[0]), "+f"((d)[1]), "+f"((d)[2]), "+f"((d)[3]) \
                 : "r"((a)[0]), "r"((a)[1]), "r"((a)[2]), "r"((a)[3]), \
                   "r"((b)[0]), "r"((b)[1]))

// 128-byte rows, 8-chunk swizzle
__device__ __forceinline__ uint32_t swz8(int row, int c16) {
    return (uint32_t)(row * 128 + ((c16 ^ (row & 7)) * 16));
}

// =================== conversion kernels =====================================
__global__ void split_kernel(const float* __restrict__ A,
                             __nv_bfloat162* __restrict__ H,
                             __nv_bfloat162* __restrict__ L, int n4)
{
    int i = blockIdx.x * blockDim.x + threadIdx.x;
    if (i >= n4) return;
    float4 v = reinterpret_cast<const float4*>(A)[i];
    __nv_bfloat16 h0 = __float2bfloat16(v.x);
    __nv_bfloat16 h1 = __float2bfloat16(v.y);
    __nv_bfloat16 h2 = __float2bfloat16(v.z);
    __nv_bfloat16 h3 = __float2bfloat16(v.w);
    __nv_bfloat16 l0 = __float2bfloat16(v.x - __bfloat162float(h0));
    __nv_bfloat16 l1 = __float2bfloat16(v.y - __bfloat162float(h1));
    __nv_bfloat16 l2 = __float2bfloat16(v.z - __bfloat162float(h2));
    __nv_bfloat16 l3 = __float2bfloat16(v.w - __bfloat162float(h3));
    H[2 * i]     = __nv_bfloat162(h0, h1);
    H[2 * i + 1] = __nv_bfloat162(h2, h3);
    L[2 * i]     = __nv_bfloat162(l0, l1);
    L[2 * i + 1] = __nv_bfloat162(l2, l3);
}

// merged Wq/Wk/Wv transpose+split in ONE launch (verified R13)
__global__ void transpose_split3(const float* __restrict__ Wq,
                                 const float* __restrict__ Wk,
                                 const float* __restrict__ Wv,
                                 __nv_bfloat16* __restrict__ Th,
                                 __nv_bfloat16* __restrict__ Tl)
{
    __shared__ float tile[32][33];
    int bx = blockIdx.x;
    const float* W;
    int N, rowoff;
    if (bx < 64)      { W = Wq; N = DMODEL; rowoff = 0; }
    else if (bx < 80) { W = Wk; N = KVDIM;  rowoff = DMODEL;        bx -= 64; }
    else              { W = Wv; N = KVDIM;  rowoff = DMODEL + KVDIM; bx -= 80; }

    int n = bx * 32 + threadIdx.x;
    int k = blockIdx.y * 32 + threadIdx.y;
#pragma unroll
    for (int j = 0; j < 32; j += 8)
        tile[threadIdx.y + j][threadIdx.x] = W[(size_t)(k + j) * N + n];
    __syncthreads();
    int k2 = blockIdx.y * 32 + threadIdx.x;
    int n2 = bx * 32 + threadIdx.y + rowoff;
#pragma unroll
    for (int j = 0; j < 32; j += 8) {
        float v = tile[threadIdx.x][threadIdx.y + j];
        __nv_bfloat16 h = __float2bfloat16(v);
        Th[(size_t)(n2 + j) * DMODEL + k2] = h;
        Tl[(size_t)(n2 + j) * DMODEL + k2] =
            __float2bfloat16(v - __bfloat162float(h));
    }
}

// single-launch transpose_split for Wo (verified)
__global__ void transpose_split(const float* __restrict__ W,
                                __nv_bfloat16* __restrict__ Th,
                                __nv_bfloat16* __restrict__ Tl, int N, int rowoff)
{
    __shared__ float tile[32][33];
    int n = blockIdx.x * 32 + threadIdx.x;
    int k = blockIdx.y * 32 + threadIdx.y;
#pragma unroll
    for (int j = 0; j < 32; j += 8)
        tile[threadIdx.y + j][threadIdx.x] = W[(size_t)(k + j) * N + n];
    __syncthreads();
    int k2 = blockIdx.y * 32 + threadIdx.x;
    int n2 = blockIdx.x * 32 + threadIdx.y + rowoff;
#pragma unroll
    for (int j = 0; j < 32; j += 8) {
        float v = tile[threadIdx.x][threadIdx.y + j];
        __nv_bfloat16 h = __float2bfloat16(v);
        Th[(size_t)(n2 + j) * DMODEL + k2] = h;
        Tl[(size_t)(n2 + j) * DMODEL + k2] =
            __float2bfloat16(v - __bfloat162float(h));
    }
}

// merged QKV postprocess, VECTORIZED: one thread = 4 consecutive rope pairs
// (float4 loads, 8-byte stores) or one V float4 granule.
// Region decode on global index:
//   [0, TOK*256)             : Q rope quads  (32 heads * 8 quads / token)
//   [TOK*256, TOK*320)       : K rope quads  ( 8 heads * 8 quads / token)
//   [TOK*320, TOK*448)       : V float4 split (128 / token)
#define QKVPP_TOTAL (TOK * 448)
__global__ void qkv_post(const float* __restrict__ QKV,
                         const float* __restrict__ cs,
                         const float* __restrict__ sn,
                         __nv_bfloat16* __restrict__ Qh, __nv_bfloat16* __restrict__ Ql,
                         __nv_bfloat16* __restrict__ Kh, __nv_bfloat16* __restrict__ Kl,
                         __nv_bfloat162* __restrict__ Vh, __nv_bfloat162* __restrict__ Vl)
{
    int idx = blockIdx.x * blockDim.x + threadIdx.x;
    if (idx >= QKVPP_TOTAL) return;

    if (idx < TOK * 320) {
        // rope quad: 4 consecutive pair-indices i0..i0+3
        bool isQ = (idx < TOK * 256);
        int r   = isQ ? idx : idx - TOK * 256;
        int nh  = isQ ? 32 : 8;
        int q   = r & 7;            // quad index -> i0 = q*4
        int h   = (r >> 3) % nh;
        int t   = r / (8 * nh);
        int i0  = q * 4;
        int xoff = isQ ? 0 : DMODEL;
        int ostr = isQ ? DMODEL : KVDIM;
        float scale = isQ ? ATTN_SCALE : 1.0f;
        __nv_bfloat16* Xh = isQ ? Qh : Kh;
        __nv_bfloat16* Xl = isQ ? Ql : Kl;

        float4 cv = *reinterpret_cast<const float4*>(cs + t * 32 + i0);
        float4 sv = *reinterpret_cast<const float4*>(sn + t * 32 + i0);
        const float* in = QKV + (size_t)t * QKVN + xoff + h * HDIM;
        float4 x1 = *reinterpret_cast<const float4*>(in + i0);
        float4 x2 = *reinterpret_cast<const float4*>(in + i0 + 32);

        float y1[4], y2[4];
        y1[0] = (x1.x * cv.x - x2.x * sv.x) * scale;
        y1[1] = (x1.y * cv.y - x2.y * sv.y) * scale;
        y1[2] = (x1.z * cv.z - x2.z * sv.z) * scale;
        y1[3] = (x1.w * cv.w - x2.w * sv.w) * scale;
        y2[0] = (x2.x * cv.x + x1.x * sv.x) * scale;
        y2[1] = (x2.y * cv.y + x1.y * sv.y) * scale;
        y2[2] = (x2.z * cv.z + x1.z * sv.z) * scale;
        y2[3] = (x2.w * cv.w + x1.w * sv.w) * scale;

        size_t ob = (size_t)t * ostr + h * HDIM + i0;
        __nv_bfloat162 h1a = __floats2bfloat162_rn(y1[0], y1[1]);
        __nv_bfloat162 h1b = __floats2bfloat162_rn(y1[2], y1[3]);
        __nv_bfloat162 h2a = __floats2bfloat162_rn(y2[0], y2[1]);
        __nv_bfloat162 h2b = __floats2bfloat162_rn(y2[2], y2[3]);
        *reinterpret_cast<__nv_bfloat162*>(Xh + ob)          = h1a;
        *reinterpret_cast<__nv_bfloat162*>(Xh + ob + 2)      = h1b;
        *reinterpret_cast<__nv_bfloat162*>(Xh + ob + 32)     = h2a;
        *reinterpret_cast<__nv_bfloat162*>(Xh + ob + 34)     = h2b;
        __nv_bfloat162 l1a = __floats2bfloat162_rn(
            y1[0] - __bfloat162float(h1a.x), y1[1] - __bfloat162float(h1a.y));
        __nv_bfloat162 l1b = __floats2bfloat162_rn(
            y1[2] - __bfloat162float(h1b.x), y1[3] - __bfloat162float(h1b.y));
        __nv_bfloat162 l2a = __floats2bfloat162_rn(
            y2[0] - __bfloat162float(h2a.x), y2[1] - __bfloat162float(h2a.y));
        __nv_bfloat162 l2b = __floats2bfloat162_rn(
            y2[2] - __bfloat162float(h2b.x), y2[3] - __bfloat162float(h2b.y));
        *reinterpret_cast<__nv_bfloat162*>(Xl + ob)          = l1a;
        *reinterpret_cast<__nv_bfloat162*>(Xl + ob + 2)      = l1b;
        *reinterpret_cast<__nv_bfloat162*>(Xl + ob + 32)     = l2a;
        *reinterpret_cast<__nv_bfloat162*>(Xl + ob + 34)     = l2b;
    } else {
        // V split (float4 granules)
        int r = idx - TOK * 320;
        int c = r & 127;
        int t = r >> 7;
        float4 v = *reinterpret_cast<const float4*>(
            QKV + (size_t)t * QKVN + DMODEL + KVDIM + c * 4);
        __nv_bfloat16 h0 = __float2bfloat16(v.x);
        __nv_bfloat16 h1 = __float2bfloat16(v.y);
        __nv_bfloat16 h2 = __float2bfloat16(v.z);
        __nv_bfloat16 h3 = __float2bfloat16(v.w);
        size_t o = ((size_t)t * KVDIM + c * 4) / 2;
        Vh[o]     = __nv_bfloat162(h0, h1);
        Vh[o + 1] = __nv_bfloat162(h2, h3);
        Vl[o]     = __nv_bfloat162(__float2bfloat16(v.x - __bfloat162float(h0)),
                                   __float2bfloat16(v.y - __bfloat162float(h1)));
        Vl[o + 1] = __nv_bfloat162(__float2bfloat16(v.z - __bfloat162float(h2)),
                                   __float2bfloat16(v.w - __bfloat162float(h3)));
    }
}

// =================== HMMA GEMM (verified R8/R13 mainloop) ===================
#define BM 128
#define BN 128
#define BK 64
#define TILE_B (128 * BK * 2)          // 16384
#define STAGE_B (4 * TILE_B)           // 65536
#define GEMM_SMEM (3 * STAGE_B)        // 196608

__device__ __forceinline__ void stage_load(
    const __nv_bfloat16* __restrict__ aH, const __nv_bfloat16* __restrict__ aL,
    const __nv_bfloat16* __restrict__ bH, const __nv_bfloat16* __restrict__ bL,
    uint32_t sbase, int k0, int tid)
{
#pragma unroll
    for (int j = 0; j < 4; j++) {
        int i = tid + j * 256;
        int row = i >> 3;
        int c16 = i & 7;
        uint32_t doff = swz8(row, c16);
        size_t goff = (size_t)row * DMODEL + k0 + c16 * 8;
        CP_ASYNC16(sbase + 0 * TILE_B + doff, aH + goff);
        CP_ASYNC16(sbase + 1 * TILE_B + doff, aL + goff);
        CP_ASYNC16(sbase + 2 * TILE_B + doff, bH + goff);
        CP_ASYNC16(sbase + 3 * TILE_B + doff, bL + goff);
    }
}

__global__ void __launch_bounds__(256, 1) gemm_mma(
    const __nv_bfloat16* __restrict__ Ahi, const __nv_bfloat16* __restrict__ Alo,
    const __nv_bfloat16* __restrict__ Bhi, const __nv_bfloat16* __restrict__ Blo,
    float* __restrict__ C, int N)
{
    extern __shared__ char smem[];
    uint32_t sb = smem_u32(smem);
    const int tid = threadIdx.x;
    const int lane = tid & 31;
    const int wid = tid >> 5;
    const int wm = wid >> 2;
    const int wn = wid & 3;
    const int brow = blockIdx.y * BM;
    const int bcol = blockIdx.x * BN;

    const __nv_bfloat16* aH = Ahi + (size_t)brow * DMODEL;
    const __nv_bfloat16* aL = Alo + (size_t)brow * DMODEL;
    const __nv_bfloat16* bH = Bhi + (size_t)bcol * DMODEL;
    const __nv_bfloat16* bL = Blo + (size_t)bcol * DMODEL;

    float acc[4][4][4];
#pragma unroll
    for (int i = 0; i < 4; i++)
#pragma unroll
        for (int j = 0; j < 4; j++)
#pragma unroll
            for (int q = 0; q < 4; q++) acc[i][j][q] = 0.f;

    const int NC = DMODEL / BK;   // 32
#pragma unroll
    for (int s = 0; s < 3; s++) {
        stage_load(aH, aL, bH, bL, sb + s * STAGE_B, s * BK, tid);
        CP_COMMIT();
    }

    for (int c = 0; c < NC; c++) {
        if (c + 2 < NC)      CP_WAIT2();
        else if (c + 1 < NC) CP_WAIT1();
        else                 CP_WAIT0();
        __syncthreads();

        uint32_t st = sb + (uint32_t)(c % 3) * STAGE_B;

#pragma unroll
        for (int ks = 0; ks < 4; ks++) {
            uint32_t fAh[4][4], fAl[4][4];
#pragma unroll
            for (int mt = 0; mt < 4; mt++) {
                int row = wm * 64 + mt * 16 + (lane & 15);
                int c16 = ks * 2 + (lane >> 4);
                uint32_t off = swz8(row, c16);
                LDMATRIX_X4(fAh[mt][0], fAh[mt][1], fAh[mt][2], fAh[mt][3],
                            st + 0 * TILE_B + off);
                LDMATRIX_X4(fAl[mt][0], fAl[mt][1], fAl[mt][2], fAl[mt][3],
                            st + 1 * TILE_B + off);
            }
            uint32_t fBh[4][2], fBl[4][2];
#pragma unroll
            for (int pr = 0; pr < 2; pr++) {
                int nrel = wn * 32 + pr * 16 + ((lane >> 4) * 8 + (lane & 7));
                int c16 = ks * 2 + ((lane >> 3) & 1);
                uint32_t off = swz8(nrel, c16);
                LDMATRIX_X4(fBh[2 * pr][0], fBh[2 * pr][1],
                            fBh[2 * pr + 1][0], fBh[2 * pr + 1][1],
                            st + 2 * TILE_B + off);
                LDMATRIX_X4(fBl[2 * pr][0], fBl[2 * pr][1],
                            fBl[2 * pr + 1][0], fBl[2 * pr + 1][1],
                            st + 3 * TILE_B + off);
            }
#pragma unroll
            for (int mt = 0; mt < 4; mt++)
#pragma unroll
                for (int nt = 0; nt < 4; nt++) {
                    MMA16816(acc[mt][nt], fAh[mt], fBh[nt]);
                    MMA16816(acc[mt][nt], fAh[mt], fBl[nt]);
                    MMA16816(acc[mt][nt], fAl[mt], fBh[nt]);
                }
        }
        __syncthreads();
        if (c + 3 < NC) {
            stage_load(aH, aL, bH, bL, st, (c + 3) * BK, tid);
            CP_COMMIT();
        }
    }

#pragma unroll
    for (int mt = 0; mt < 4; mt++) {
#pragma unroll
        for (int nt = 0; nt < 4; nt++) {
            int m = brow + wm * 64 + mt * 16 + (lane >> 2);
            int n = bcol + wn * 32 + nt * 8 + (lane & 3) * 2;
            float2 v0 = make_float2(acc[mt][nt][0], acc[mt][nt][1]);
            float2 v1 = make_float2(acc[mt][nt][2], acc[mt][nt][3]);
            *reinterpret_cast<float2*>(C + (size_t)m * N + n) = v0;
            *reinterpret_cast<float2*>(C + (size_t)(m + 8) * N + n) = v1;
        }
    }
}

// =================== tensor-core flash attention (verified R13) =============
#define FQ_SMEM 32768
#define KV_BUF  32768
#define FLASH_SMEM (FQ_SMEM + 2 * KV_BUF)

__device__ __forceinline__ void stage_kv(
    const __nv_bfloat16* __restrict__ Kh, const __nv_bfloat16* __restrict__ Kl,
    const __nv_bfloat16* __restrict__ Vh, const __nv_bfloat16* __restrict__ Vl,
    uint32_t sbase, size_t gbase, int tid)
{
#pragma unroll
    for (int t = 0; t < 4; t++) {
        int i = tid + t * 128;
        int row = i >> 3;
        int c16 = i & 7;
        uint32_t doff = swz8(row, c16);
        size_t goff = gbase + (size_t)row * KVDIM + c16 * 8;
        CP_ASYNC16(sbase + 0     + doff, Kh + goff);
        CP_ASYNC16(sbase + 8192  + doff, Kl + goff);
        CP_ASYNC16(sbase + 16384 + doff, Vh + goff);
        CP_ASYNC16(sbase + 24576 + doff, Vl + goff);
    }
}

__global__ void __launch_bounds__(128) flash_mma(
    const __nv_bfloat16* __restrict__ Qh, const __nv_bfloat16* __restrict__ Ql,
    const __nv_bfloat16* __restrict__ Kh, const __nv_bfloat16* __restrict__ Kl,
    const __nv_bfloat16* __restrict__ Vh, const __nv_bfloat16* __restrict__ Vl,
    __nv_bfloat16* __restrict__ Oh, __nv_bfloat16* __restrict__ Ol)
{
    extern __shared__ char smem[];
    uint32_t sb = smem_u32(smem);
    const int qt = (int)gridDim.x - 1 - (int)blockIdx.x;   // LPT
    const int h  = blockIdx.y;
    const int b  = blockIdx.z;
    const int kvh = h / GROUPS;
    const int tid = threadIdx.x;
    const int lane = tid & 31;
    const int w = tid >> 5;
    const int qbase = qt * 128;

#pragma unroll
    for (int t = 0; t < 8; t++) {
        int i = tid + t * 128;
        int row = i >> 3;
        int c16 = i & 7;
        uint32_t doff = swz8(row, c16);
        size_t goff = (size_t)(b * SEQ + qbase + row) * DMODEL + h * HDIM + c16 * 8;
        CP_ASYNC16(sb + doff, Qh + goff);
        CP_ASYNC16(sb + 16384 + doff, Ql + goff);
    }
    size_t kvg0 = (size_t)(b * SEQ) * KVDIM + kvh * HDIM;
    stage_kv(Kh, Kl, Vh, Vl, sb + FQ_SMEM, kvg0, tid);
    CP_COMMIT();

    float acc[2][8][4];
#pragma unroll
    for (int mt = 0; mt < 2; mt++)
#pragma unroll
        for (int nt = 0; nt < 8; nt++)
#pragma unroll
            for (int e = 0; e < 4; e++) acc[mt][nt][e] = 0.f;
    float mrow[2][2] = {{-CUDART_INF_F, -CUDART_INF_F},
                        {-CUDART_INF_F, -CUDART_INF_F}};
    float lrow[2][2] = {{0.f, 0.f}, {0.f, 0.f}};

    const int nb = 2 * qt + 2;
    for (int c = 0; c < nb; c++) {
        if (c + 1 < nb) {
            stage_kv(Kh, Kl, Vh, Vl, sb + FQ_SMEM + ((c + 1) & 1) * KV_BUF,
                     kvg0 + (size_t)(c + 1) * 64 * KVDIM, tid);
            CP_COMMIT();
            CP_WAIT1();
        } else {
            CP_WAIT0();
        }
        __syncthreads();

        uint32_t sk = sb + FQ_SMEM + (c & 1) * KV_BUF;

        float S[2][8][4];
#pragma unroll
        for (int mt = 0; mt < 2; mt++)
#pragma unroll
            for (int nt = 0; nt < 8; nt++)
#pragma unroll
                for (int e = 0; e < 4; e++) S[mt][nt][e] = 0.f;

#pragma unroll
        for (int ks = 0; ks < 4; ks++) {
            uint32_t qh[2][4], ql[2][4];
#pragma unroll
            for (int mt = 0; mt < 2; mt++) {
                int row = w * 32 + mt * 16 + (lane & 15);
                int c16 = ks * 2 + (lane >> 4);
                uint32_t off = swz8(row, c16);
                LDMATRIX_X4(qh[mt][0], qh[mt][1], qh[mt][2], qh[mt][3], sb + off);
                LDMATRIX_X4(ql[mt][0], ql[mt][1], ql[mt][2], ql[mt][3],
                            sb + 16384 + off);
            }
#pragma unroll
            for (int np = 0; np < 4; np++) {
                int row = np * 16 + ((lane >> 4) * 8) + (lane & 7);
                int c16 = ks * 2 + ((lane >> 3) & 1);
                uint32_t off = swz8(row, c16);
                uint32_t kh[4], kl[4];
                LDMATRIX_X4(kh[0], kh[1], kh[2], kh[3], sk + off);
                LDMATRIX_X4(kl[0], kl[1], kl[2], kl[3], sk + 8192 + off);
#pragma unroll
                for (int mt = 0; mt < 2; mt++) {
                    MMA16816(S[mt][2 * np],     qh[mt], (kh + 0));
                    MMA16816(S[mt][2 * np + 1], qh[mt], (kh + 2));
                    MMA16816(S[mt][2 * np],     qh[mt], (kl + 0));
                    MMA16816(S[mt][2 * np + 1], qh[mt], (kl + 2));
                    MMA16816(S[mt][2 * np],     ql[mt], (kh + 0));
                    MMA16816(S[mt][2 * np + 1], ql[mt], (kh + 2));
                }
            }
        }

        if (c >= 2 * qt) {
            int kb = c * 64;
#pragma unroll
            for (int mt = 0; mt < 2; mt++) {
                int r0 = qbase + w * 32 + mt * 16 + (lane >> 2);
#pragma unroll
                for (int nt = 0; nt < 8; nt++) {
                    int key = kb + nt * 8 + (lane & 3) * 2;
                    if (key > r0)     S[mt][nt][0] = -CUDART_INF_F;
                    if (key + 1 > r0) S[mt][nt][1] = -CUDART_INF_F;
                    if (key > r0 + 8)     S[mt][nt][2] = -CUDART_INF_F;
                    if (key + 1 > r0 + 8) S[mt][nt][3] = -CUDART_INF_F;
                }
            }
        }

        uint32_t aPh[2][4][4], aPl[2][4][4];
#pragma unroll
        for (int mt = 0; mt < 2; mt++) {
#pragma unroll
            for (int e2 = 0; e2 < 2; e2++) {
                float mx = -CUDART_INF_F;
#pragma unroll
                for (int nt = 0; nt < 8; nt++)
                    mx = fmaxf(mx, fmaxf(S[mt][nt][2 * e2], S[mt][nt][2 * e2 + 1]));
                mx = fmaxf(mx, __shfl_xor_sync(0xffffffffu, mx, 1));
                mx = fmaxf(mx, __shfl_xor_sync(0xffffffffu, mx, 2));
                float mn = fmaxf(mrow[mt][e2], mx);
                float alpha = __expf(mrow[mt][e2] - mn);
                mrow[mt][e2] = mn;
                float sum = 0.f;
#pragma unroll
                for (int nt = 0; nt < 8; nt++) {
                    float p0 = __expf(S[mt][nt][2 * e2] - mn);
                    float p1 = __expf(S[mt][nt][2 * e2 + 1] - mn);
                    S[mt][nt][2 * e2] = p0;
                    S[mt][nt][2 * e2 + 1] = p1;
                    sum += p0 + p1;
                }
                sum += __shfl_xor_sync(0xffffffffu, sum, 1);
                sum += __shfl_xor_sync(0xffffffffu, sum, 2);
                lrow[mt][e2] = lrow[mt][e2] * alpha + sum;
#pragma unroll
                for (int nt = 0; nt < 8; nt++) {
                    acc[mt][nt][2 * e2] *= alpha;
                    acc[mt][nt][2 * e2 + 1] *= alpha;
                }
            }
#pragma unroll
            for (int kc = 0; kc < 4; kc++) {
#pragma unroll
                for (int r = 0; r < 4; r++) {
                    int nt = 2 * kc + (r >> 1);
                    int e0 = (r & 1) * 2;
                    float p0 = S[mt][nt][e0], p1 = S[mt][nt][e0 + 1];
                    __nv_bfloat162 hh = __floats2bfloat162_rn(p0, p1);
                    float r0 = p0 - __bfloat162float(hh.x);
                    float r1 = p1 - __bfloat162float(hh.y);
                    __nv_bfloat162 ll = __floats2bfloat162_rn(r0, r1);
                    aPh[mt][kc][r] = *reinterpret_cast<uint32_t*>(&hh);
                    aPl[mt][kc][r] = *reinterpret_cast<uint32_t*>(&ll);
                }
            }
        }

#pragma unroll
        for (int kc = 0; kc < 4; kc++) {
#pragma unroll
            for (int dp = 0; dp < 4; dp++) {
                int row = kc * 16 + ((lane >> 3) & 1) * 8 + (lane & 7);
                int c16 = dp * 2 + (lane >> 4);
                uint32_t off = swz8(row, c16);
                uint32_t vh[4], vl[4];
                LDMATRIX_X4T(vh[0], vh[1], vh[2], vh[3], sk + 16384 + off);
                LDMATRIX_X4T(vl[0], vl[1], vl[2], vl[3], sk + 24576 + off);
#pragma unroll
                for (int mt = 0; mt < 2; mt++) {
                    MMA16816(acc[mt][2 * dp],     aPh[mt][kc], (vh + 0));
                    MMA16816(acc[mt][2 * dp + 1], aPh[mt][kc], (vh + 2));
                    MMA16816(acc[mt][2 * dp],     aPh[mt][kc], (vl + 0));
                    MMA16816(acc[mt][2 * dp + 1], aPh[mt][kc], (vl + 2));
                    MMA16816(acc[mt][2 * dp],     aPl[mt][kc], (vh + 0));
                    MMA16816(acc[mt][2 * dp + 1], aPl[mt][kc], (vh + 2));
                }
            }
        }
        __syncthreads();
    }

#pragma unroll
    for (int mt = 0; mt < 2; mt++) {
        float inv0 = 1.0f / lrow[mt][0];
        float inv1 = 1.0f / lrow[mt][1];
        int r0 = qbase + w * 32 + mt * 16 + (lane >> 2);
        size_t t0 = (size_t)(b * SEQ + r0) * DMODEL + h * HDIM;
        size_t t1 = t0 + 8 * DMODEL;
#pragma unroll
        for (int nt = 0; nt < 8; nt++) {
            int d = nt * 8 + (lane & 3) * 2;
            float v0 = acc[mt][nt][0] * inv0, v1 = acc[mt][nt][1] * inv0;
            float v2 = acc[mt][nt][2] * inv1, v3 = acc[mt][nt][3] * inv1;
            __nv_bfloat162 h01 = __floats2bfloat162_rn(v0, v1);
            __nv_bfloat162 h23 = __floats2bfloat162_rn(v2, v3);
            __nv_bfloat162 l01 = __floats2bfloat162_rn(
                v0 - __bfloat162float(h01.x), v1 - __bfloat162float(h01.y));
            __nv_bfloat162 l23 = __floats2bfloat162_rn(
                v2 - __bfloat162float(h23.x), v3 - __bfloat162float(h23.y));
            *reinterpret_cast<__nv_bfloat162*>(Oh + t0 + d) = h01;
            *reinterpret_cast<__nv_bfloat162*>(Oh + t1 + d) = h23;
            *reinterpret_cast<__nv_bfloat162*>(Ol + t0 + d) = l01;
            *reinterpret_cast<__nv_bfloat162*>(Ol + t1 + d) = l23;
        }
    }
}

// ---------------- launch ----------------------------------------------------
extern "C" void kernel_launch(void* const* d_in, const int* in_sizes, int n_in,
                              void* d_out, int out_size)
{
    const float* hidden = (const float*)d_in[0];
    const float* cs     = (const float*)d_in[1];
    const float* sn     = (const float*)d_in[2];
    const float* Wq     = (const float*)d_in[3];
    const float* Wk     = (const float*)d_in[4];
    const float* Wv     = (const float*)d_in[5];
    const float* Wo     = (const float*)d_in[6];
    float* out          = (float*)d_out;

    float* QKV = nullptr; cudaGetSymbolAddress((void**)&QKV, g_QKV);
    __nv_bfloat16* Ah = nullptr; cudaGetSymbolAddress((void**)&Ah, g_Ahi);
    __nv_bfloat16* Al = nullptr; cudaGetSymbolAddress((void**)&Al, g_Alo);
    __nv_bfloat16* Bh = nullptr; cudaGetSymbolAddress((void**)&Bh, g_Bhi);
    __nv_bfloat16* Bl = nullptr; cudaGetSymbolAddress((void**)&Bl, g_Blo);
    __nv_bfloat16* Qh = nullptr; cudaGetSymbolAddress((void**)&Qh, g_Qh);
    __nv_bfloat16* Ql = nullptr; cudaGetSymbolAddress((void**)&Ql, g_Ql);
    __nv_bfloat16* Kh = nullptr; cudaGetSymbolAddress((void**)&Kh, g_Kh);
    __nv_bfloat16* Kl = nullptr; cudaGetSymbolAddress((void**)&Kl, g_Kl);
    __nv_bfloat16* Vh = nullptr; cudaGetSymbolAddress((void**)&Vh, g_Vh);
    __nv_bfloat16* Vl = nullptr; cudaGetSymbolAddress((void**)&Vl, g_Vl);

    static bool attr_set = false;
    if (!attr_set) {
        cudaFuncSetAttribute(gemm_mma, cudaFuncAttributeMaxDynamicSharedMemorySize,
                             GEMM_SMEM);
        cudaFuncSetAttribute(flash_mma, cudaFuncAttributeMaxDynamicSharedMemorySize,
                             FLASH_SMEM);
        attr_set = true;
    }

    const int n4 = TOK * DMODEL / 4;

    // hidden -> bf16 hi/lo (A operand)
    split_kernel<<<n4 / 256, 256>>>(hidden, (__nv_bfloat162*)Ah,
                                    (__nv_bfloat162*)Al, n4);

    // B = [WqT ; WkT ; WvT] in ONE launch
    transpose_split3<<<dim3(96, DMODEL / 32), dim3(32, 8)>>>(Wq, Wk, Wv, Bh, Bl);

    // fused QKV GEMM
    gemm_mma<<<dim3(QKVN / BN, TOK / BM), 256, GEMM_SMEM>>>(Ah, Al, Bh, Bl, QKV, QKVN);

    // merged postprocess (vectorized): Q rope + K rope + V split, ONE launch
    qkv_post<<<(QKVPP_TOTAL + 255) / 256, 256>>>(QKV, cs, sn, Qh, Ql, Kh, Kl,
                                                 (__nv_bfloat162*)Vh,
                                                 (__nv_bfloat162*)Vl);

    // Wo transpose (Bh/Bl free after QKV GEMM)
    transpose_split<<<dim3(DMODEL / 32, DMODEL / 32), dim3(32, 8)>>>(Wo, Bh, Bl, DMODEL, 0);

    // flash attention (LPT) -> writes bf16 hi/lo into Wo-GEMM A buffers
    {
        dim3 grid(SEQ / 128, NHEADS, BSZ);
        flash_mma<<<grid, 128, FLASH_SMEM>>>(Qh, Ql, Kh, Kl, Vh, Vl, Ah, Al);
    }

    // out = attn @ Wo
    gemm_mma<<<dim3(DMODEL / BN, TOK / BM), 256, GEMM_SMEM>>>(Ah, Al, Bh, Bl, out, DMODEL);
}

// round 16
// speedup vs baseline: 1.1387x; 1.0062x over previous
#include <cuda_runtime.h>
#include <cuda_bf16.h>
#include <cstdint>
#include <math_constants.h>

// Problem constants
#define BSZ 4
#define SEQ 1024
#define TOK (BSZ * SEQ)          // 4096
#define DMODEL 2048
#define NHEADS 32
#define NKV 8
#define HDIM 64
#define GROUPS (NHEADS / NKV)     // 4
#define KVDIM (NKV * HDIM)        // 512
#define QKVN (DMODEL + 2 * KVDIM) // 3072
#define ATTN_SCALE 0.125f

// ---------------- scratch (static device globals; no allocation) ----------
__device__ float g_QKV[(size_t)TOK * QKVN];
__device__ __align__(16) __nv_bfloat16 g_Ahi[(size_t)TOK * DMODEL];
__device__ __align__(16) __nv_bfloat16 g_Alo[(size_t)TOK * DMODEL];
__device__ __align__(16) __nv_bfloat16 g_Bhi[(size_t)QKVN * DMODEL]; // [N,K]
__device__ __align__(16) __nv_bfloat16 g_Blo[(size_t)QKVN * DMODEL];
__device__ __align__(16) __nv_bfloat16 g_Qh[(size_t)TOK * DMODEL];
__device__ __align__(16) __nv_bfloat16 g_Ql[(size_t)TOK * DMODEL];
__device__ __align__(16) __nv_bfloat16 g_Kh[(size_t)TOK * KVDIM];
__device__ __align__(16) __nv_bfloat16 g_Kl[(size_t)TOK * KVDIM];
__device__ __align__(16) __nv_bfloat16 g_Vh[(size_t)TOK * KVDIM];
__device__ __align__(16) __nv_bfloat16 g_Vl[(size_t)TOK * KVDIM];

// =================== PTX helpers (compute_103-safe) =========================
__device__ __forceinline__ uint32_t smem_u32(const void* p) {
    uint32_t a;
    asm("{ .reg .u64 t; cvta.to.shared.u64 t, %1; cvt.u32.u64 %0, t; }"
        : "=r"(a) : "l"(p));
    return a;
}

#define CP_ASYNC16(dst, src) \
    asm volatile("cp.async.cg.shared.global [%0], [%1], 16;" \
                 :: "r"(dst), "l"(src) : "memory")
#define CP_COMMIT() asm volatile("cp.async.commit_group;" ::: "memory")
#define CP_WAIT2()  asm volatile("cp.async.wait_group 2;" ::: "memory")
#define CP_WAIT1()  asm volatile("cp.async.wait_group 1;" ::: "memory")
#define CP_WAIT0()  asm volatile("cp.async.wait_group 0;" ::: "memory")

#define LDMATRIX_X4(r0, r1, r2, r3, addr) \
    asm volatile("ldmatrix.sync.aligned.m8n8.x4.shared.b16 {%0,%1,%2,%3}, [%4];" \
                 : "=r"(r0), "=r"(r1), "=r"(r2), "=r"(r3) : "r"(addr))

#define LDMATRIX_X4T(r0, r1, r2, r3, addr) \
    asm volatile("ldmatrix.sync.aligned.m8n8.x4.trans.shared.b16 {%0,%1,%2,%3}, [%4];" \
                 : "=r"(r0), "=r"(r1), "=r"(r2), "=r"(r3) : "r"(addr))

#define MMA16816(d, a, b) \
    asm volatile("mma.sync.aligned.m16n8k16.row.col.f32.bf16.bf16.f32 " \
                 "{%0,%1,%2,%3}, {%4,%5,%6,%7}, {%8,%9}, {%0,%1,%2,%3};" \
                 : "+f"((d)[0]), "+f"((d)[1]), "+f"((d)[2]), "+f"((d)[3]) \
                 : "r"((a)[0]), "r"((a)[1]), "r"((a)[2]), "r"((a)[3]), \
                   "r"((b)[0]), "r"((b)[1]))

// 128-byte rows, 8-chunk swizzle
__device__ __forceinline__ uint32_t swz8(int row, int c16) {
    return (uint32_t)(row * 128 + ((c16 ^ (row & 7)) * 16));
}

// =================== merged prep: hidden split + Wq/Wk/Wv transpose ========
// blocks [0, 8192)       : hidden fp32 -> bf16 hi/lo (float4 granules)
// blocks [8192, 14336)   : transpose_split3 region (6144 = 96 x 64 tiles)
#define SPLIT_BLOCKS 8192
#define PREP_BLOCKS (SPLIT_BLOCKS + 96 * 64)

__global__ void prep_kernel(const float* __restrict__ hidden,
                            __nv_bfloat162* __restrict__ H,
                            __nv_bfloat162* __restrict__ L,
                            const float* __restrict__ Wq,
                            const float* __restrict__ Wk,
                            const float* __restrict__ Wv,
                            __nv_bfloat16* __restrict__ Th,
                            __nv_bfloat16* __restrict__ Tl)
{
    __shared__ float tile[32][33];
    int blk = blockIdx.x;
    int tid = threadIdx.x;

    if (blk < SPLIT_BLOCKS) {
        int i = blk * 256 + tid;            // n4 = 8192*256 exactly
        float4 v = reinterpret_cast<const float4*>(hidden)[i];
        __nv_bfloat16 h0 = __float2bfloat16(v.x);
        __nv_bfloat16 h1 = __float2bfloat16(v.y);
        __nv_bfloat16 h2 = __float2bfloat16(v.z);
        __nv_bfloat16 h3 = __float2bfloat16(v.w);
        H[2 * i]     = __nv_bfloat162(h0, h1);
        H[2 * i + 1] = __nv_bfloat162(h2, h3);
        L[2 * i]     = __nv_bfloat162(__float2bfloat16(v.x - __bfloat162float(h0)),
                                      __float2bfloat16(v.y - __bfloat162float(h1)));
        L[2 * i + 1] = __nv_bfloat162(__float2bfloat16(v.z - __bfloat162float(h2)),
                                      __float2bfloat16(v.w - __bfloat162float(h3)));
        return;
    }

    // transpose_split3 region
    int r = blk - SPLIT_BLOCKS;
    int bx = r % 96;
    int by = r / 96;                        // 0..63 (k tiles)
    int tx = tid & 31;
    int ty = tid >> 5;                      // 0..7

    const float* W;
    int N, rowoff;
    if (bx < 64)      { W = Wq; N = DMODEL; rowoff = 0; }
    else if (bx < 80) { W = Wk; N = KVDIM;  rowoff = DMODEL;         bx -= 64; }
    else              { W = Wv; N = KVDIM;  rowoff = DMODEL + KVDIM; bx -= 80; }

    int n = bx * 32 + tx;
    int k = by * 32 + ty;
#pragma unroll
    for (int j = 0; j < 32; j += 8)
        tile[ty + j][tx] = W[(size_t)(k + j) * N + n];
    __syncthreads();
    int k2 = by * 32 + tx;
    int n2 = bx * 32 + ty + rowoff;
#pragma unroll
    for (int j = 0; j < 32; j += 8) {
        float v = tile[tx][ty + j];
        __nv_bfloat16 h = __float2bfloat16(v);
        Th[(size_t)(n2 + j) * DMODEL + k2] = h;
        Tl[(size_t)(n2 + j) * DMODEL + k2] =
            __float2bfloat16(v - __bfloat162float(h));
    }
}

// =================== merged post: qkv_post + Wo transpose ===================
// blocks [0, 7168)        : vectorized qkv_post (TOK*448 = 7168*256 exactly)
// blocks [7168, 11264)    : Wo transpose_split (4096 = 64 x 64 tiles)
#define QKVPP_BLOCKS 7168
#define POST_BLOCKS (QKVPP_BLOCKS + 64 * 64)

__global__ void post_kernel(const float* __restrict__ QKV,
                            const float* __restrict__ cs,
                            const float* __restrict__ sn,
                            __nv_bfloat16* __restrict__ Qh, __nv_bfloat16* __restrict__ Ql,
                            __nv_bfloat16* __restrict__ Kh, __nv_bfloat16* __restrict__ Kl,
                            __nv_bfloat162* __restrict__ Vh, __nv_bfloat162* __restrict__ Vl,
                            const float* __restrict__ Wo,
                            __nv_bfloat16* __restrict__ Th,
                            __nv_bfloat16* __restrict__ Tl)
{
    __shared__ float tile[32][33];
    int blk = blockIdx.x;
    int tid = threadIdx.x;

    if (blk < QKVPP_BLOCKS) {
        int idx = blk * 256 + tid;

        if (idx < TOK * 320) {
            // rope quad: 4 consecutive pair-indices i0..i0+3
            bool isQ = (idx < TOK * 256);
            int r   = isQ ? idx : idx - TOK * 256;
            int nh  = isQ ? 32 : 8;
            int q   = r & 7;
            int h   = (r >> 3) % nh;
            int t   = r / (8 * nh);
            int i0  = q * 4;
            int xoff = isQ ? 0 : DMODEL;
            int ostr = isQ ? DMODEL : KVDIM;
            float scale = isQ ? ATTN_SCALE : 1.0f;
            __nv_bfloat16* Xh = isQ ? Qh : Kh;
            __nv_bfloat16* Xl = isQ ? Ql : Kl;

            float4 cv = *reinterpret_cast<const float4*>(cs + t * 32 + i0);
            float4 sv = *reinterpret_cast<const float4*>(sn + t * 32 + i0);
            const float* in = QKV + (size_t)t * QKVN + xoff + h * HDIM;
            float4 x1 = *reinterpret_cast<const float4*>(in + i0);
            float4 x2 = *reinterpret_cast<const float4*>(in + i0 + 32);

            float y1[4], y2[4];
            y1[0] = (x1.x * cv.x - x2.x * sv.x) * scale;
            y1[1] = (x1.y * cv.y - x2.y * sv.y) * scale;
            y1[2] = (x1.z * cv.z - x2.z * sv.z) * scale;
            y1[3] = (x1.w * cv.w - x2.w * sv.w) * scale;
            y2[0] = (x2.x * cv.x + x1.x * sv.x) * scale;
            y2[1] = (x2.y * cv.y + x1.y * sv.y) * scale;
            y2[2] = (x2.z * cv.z + x1.z * sv.z) * scale;
            y2[3] = (x2.w * cv.w + x1.w * sv.w) * scale;

            size_t ob = (size_t)t * ostr + h * HDIM + i0;
            __nv_bfloat162 h1a = __floats2bfloat162_rn(y1[0], y1[1]);
            __nv_bfloat162 h1b = __floats2bfloat162_rn(y1[2], y1[3]);
            __nv_bfloat162 h2a = __floats2bfloat162_rn(y2[0], y2[1]);
            __nv_bfloat162 h2b = __floats2bfloat162_rn(y2[2], y2[3]);
            *reinterpret_cast<__nv_bfloat162*>(Xh + ob)      = h1a;
            *reinterpret_cast<__nv_bfloat162*>(Xh + ob + 2)  = h1b;
            *reinterpret_cast<__nv_bfloat162*>(Xh + ob + 32) = h2a;
            *reinterpret_cast<__nv_bfloat162*>(Xh + ob + 34) = h2b;
            __nv_bfloat162 l1a = __floats2bfloat162_rn(
                y1[0] - __bfloat162float(h1a.x), y1[1] - __bfloat162float(h1a.y));
            __nv_bfloat162 l1b = __floats2bfloat162_rn(
                y1[2] - __bfloat162float(h1b.x), y1[3] - __bfloat162float(h1b.y));
            __nv_bfloat162 l2a = __floats2bfloat162_rn(
                y2[0] - __bfloat162float(h2a.x), y2[1] - __bfloat162float(h2a.y));
            __nv_bfloat162 l2b = __floats2bfloat162_rn(
                y2[2] - __bfloat162float(h2b.x), y2[3] - __bfloat162float(h2b.y));
            *reinterpret_cast<__nv_bfloat162*>(Xl + ob)      = l1a;
            *reinterpret_cast<__nv_bfloat162*>(Xl + ob + 2)  = l1b;
            *reinterpret_cast<__nv_bfloat162*>(Xl + ob + 32) = l2a;
            *reinterpret_cast<__nv_bfloat162*>(Xl + ob + 34) = l2b;
        } else {
            // V split (float4 granules)
            int r = idx - TOK * 320;
            int c = r & 127;
            int t = r >> 7;
            float4 v = *reinterpret_cast<const float4*>(
                QKV + (size_t)t * QKVN + DMODEL + KVDIM + c * 4);
            __nv_bfloat16 h0 = __float2bfloat16(v.x);
            __nv_bfloat16 h1 = __float2bfloat16(v.y);
            __nv_bfloat16 h2 = __float2bfloat16(v.z);
            __nv_bfloat16 h3 = __float2bfloat16(v.w);
            size_t o = ((size_t)t * KVDIM + c * 4) / 2;
            Vh[o]     = __nv_bfloat162(h0, h1);
            Vh[o + 1] = __nv_bfloat162(h2, h3);
            Vl[o]     = __nv_bfloat162(__float2bfloat16(v.x - __bfloat162float(h0)),
                                       __float2bfloat16(v.y - __bfloat162float(h1)));
            Vl[o + 1] = __nv_bfloat162(__float2bfloat16(v.z - __bfloat162float(h2)),
                                       __float2bfloat16(v.w - __bfloat162float(h3)));
        }
        return;
    }

    // Wo transpose region
    int r = blk - QKVPP_BLOCKS;
    int bx = r & 63;
    int by = r >> 6;
    int tx = tid & 31;
    int ty = tid >> 5;

    int n = bx * 32 + tx;
    int k = by * 32 + ty;
#pragma unroll
    for (int j = 0; j < 32; j += 8)
        tile[ty + j][tx] = Wo[(size_t)(k + j) * DMODEL + n];
    __syncthreads();
    int k2 = by * 32 + tx;
    int n2 = bx * 32 + ty;
#pragma unroll
    for (int j = 0; j < 32; j += 8) {
        float v = tile[tx][ty + j];
        __nv_bfloat16 h = __float2bfloat16(v);
        Th[(size_t)(n2 + j) * DMODEL + k2] = h;
        Tl[(size_t)(n2 + j) * DMODEL + k2] =
            __float2bfloat16(v - __bfloat162float(h));
    }
}

// =================== HMMA GEMM (verified R8/R13 mainloop) ===================
#define BM 128
#define BN 128
#define BK 64
#define TILE_B (128 * BK * 2)          // 16384
#define STAGE_B (4 * TILE_B)           // 65536
#define GEMM_SMEM (3 * STAGE_B)        // 196608

__device__ __forceinline__ void stage_load(
    const __nv_bfloat16* __restrict__ aH, const __nv_bfloat16* __restrict__ aL,
    const __nv_bfloat16* __restrict__ bH, const __nv_bfloat16* __restrict__ bL,
    uint32_t sbase, int k0, int tid)
{
#pragma unroll
    for (int j = 0; j < 4; j++) {
        int i = tid + j * 256;
        int row = i >> 3;
        int c16 = i & 7;
        uint32_t doff = swz8(row, c16);
        size_t goff = (size_t)row * DMODEL + k0 + c16 * 8;
        CP_ASYNC16(sbase + 0 * TILE_B + doff, aH + goff);
        CP_ASYNC16(sbase + 1 * TILE_B + doff, aL + goff);
        CP_ASYNC16(sbase + 2 * TILE_B + doff, bH + goff);
        CP_ASYNC16(sbase + 3 * TILE_B + doff, bL + goff);
    }
}

__global__ void __launch_bounds__(256, 1) gemm_mma(
    const __nv_bfloat16* __restrict__ Ahi, const __nv_bfloat16* __restrict__ Alo,
    const __nv_bfloat16* __restrict__ Bhi, const __nv_bfloat16* __restrict__ Blo,
    float* __restrict__ C, int N)
{
    extern __shared__ char smem[];
    uint32_t sb = smem_u32(smem);
    const int tid = threadIdx.x;
    const int lane = tid & 31;
    const int wid = tid >> 5;
    const int wm = wid >> 2;
    const int wn = wid & 3;
    const int brow = blockIdx.y * BM;
    const int bcol = blockIdx.x * BN;

    const __nv_bfloat16* aH = Ahi + (size_t)brow * DMODEL;
    const __nv_bfloat16* aL = Alo + (size_t)brow * DMODEL;
    const __nv_bfloat16* bH = Bhi + (size_t)bcol * DMODEL;
    const __nv_bfloat16* bL = Blo + (size_t)bcol * DMODEL;

    float acc[4][4][4];
#pragma unroll
    for (int i = 0; i < 4; i++)
#pragma unroll
        for (int j = 0; j < 4; j++)
#pragma unroll
            for (int q = 0; q < 4; q++) acc[i][j][q] = 0.f;

    const int NC = DMODEL / BK;   // 32
#pragma unroll
    for (int s = 0; s < 3; s++) {
        stage_load(aH, aL, bH, bL, sb + s * STAGE_B, s * BK, tid);
        CP_COMMIT();
    }

    for (int c = 0; c < NC; c++) {
        if (c + 2 < NC)      CP_WAIT2();
        else if (c + 1 < NC) CP_WAIT1();
        else                 CP_WAIT0();
        __syncthreads();

        uint32_t st = sb + (uint32_t)(c % 3) * STAGE_B;

#pragma unroll
        for (int ks = 0; ks < 4; ks++) {
            uint32_t fAh[4][4], fAl[4][4];
#pragma unroll
            for (int mt = 0; mt < 4; mt++) {
                int row = wm * 64 + mt * 16 + (lane & 15);
                int c16 = ks * 2 + (lane >> 4);
                uint32_t off = swz8(row, c16);
                LDMATRIX_X4(fAh[mt][0], fAh[mt][1], fAh[mt][2], fAh[mt][3],
                            st + 0 * TILE_B + off);
                LDMATRIX_X4(fAl[mt][0], fAl[mt][1], fAl[mt][2], fAl[mt][3],
                            st + 1 * TILE_B + off);
            }
            uint32_t fBh[4][2], fBl[4][2];
#pragma unroll
            for (int pr = 0; pr < 2; pr++) {
                int nrel = wn * 32 + pr * 16 + ((lane >> 4) * 8 + (lane & 7));
                int c16 = ks * 2 + ((lane >> 3) & 1);
                uint32_t off = swz8(nrel, c16);
                LDMATRIX_X4(fBh[2 * pr][0], fBh[2 * pr][1],
                            fBh[2 * pr + 1][0], fBh[2 * pr + 1][1],
                            st + 2 * TILE_B + off);
                LDMATRIX_X4(fBl[2 * pr][0], fBl[2 * pr][1],
                            fBl[2 * pr + 1][0], fBl[2 * pr + 1][1],
                            st + 3 * TILE_B + off);
            }
#pragma unroll
            for (int mt = 0; mt < 4; mt++)
#pragma unroll
                for (int nt = 0; nt < 4; nt++) {
                    MMA16816(acc[mt][nt], fAh[mt], fBh[nt]);
                    MMA16816(acc[mt][nt], fAh[mt], fBl[nt]);
                    MMA16816(acc[mt][nt], fAl[mt], fBh[nt]);
                }
        }
        __syncthreads();
        if (c + 3 < NC) {
            stage_load(aH, aL, bH, bL, st, (c + 3) * BK, tid);
            CP_COMMIT();
        }
    }

#pragma unroll
    for (int mt = 0; mt < 4; mt++) {
#pragma unroll
        for (int nt = 0; nt < 4; nt++) {
            int m = brow + wm * 64 + mt * 16 + (lane >> 2);
            int n = bcol + wn * 32 + nt * 8 + (lane & 3) * 2;
            float2 v0 = make_float2(acc[mt][nt][0], acc[mt][nt][1]);
            float2 v1 = make_float2(acc[mt][nt][2], acc[mt][nt][3]);
            *reinterpret_cast<float2*>(C + (size_t)m * N + n) = v0;
            *reinterpret_cast<float2*>(C + (size_t)(m + 8) * N + n) = v1;
        }
    }
}

// =================== tensor-core flash attention (verified R13) =============
#define FQ_SMEM 32768
#define KV_BUF  32768
#define FLASH_SMEM (FQ_SMEM + 2 * KV_BUF)

__device__ __forceinline__ void stage_kv(
    const __nv_bfloat16* __restrict__ Kh, const __nv_bfloat16* __restrict__ Kl,
    const __nv_bfloat16* __restrict__ Vh, const __nv_bfloat16* __restrict__ Vl,
    uint32_t sbase, size_t gbase, int tid)
{
#pragma unroll
    for (int t = 0; t < 4; t++) {
        int i = tid + t * 128;
        int row = i >> 3;
        int c16 = i & 7;
        uint32_t doff = swz8(row, c16);
        size_t goff = gbase + (size_t)row * KVDIM + c16 * 8;
        CP_ASYNC16(sbase + 0     + doff, Kh + goff);
        CP_ASYNC16(sbase + 8192  + doff, Kl + goff);
        CP_ASYNC16(sbase + 16384 + doff, Vh + goff);
        CP_ASYNC16(sbase + 24576 + doff, Vl + goff);
    }
}

__global__ void __launch_bounds__(128) flash_mma(
    const __nv_bfloat16* __restrict__ Qh, const __nv_bfloat16* __restrict__ Ql,
    const __nv_bfloat16* __restrict__ Kh, const __nv_bfloat16* __restrict__ Kl,
    const __nv_bfloat16* __restrict__ Vh, const __nv_bfloat16* __restrict__ Vl,
    __nv_bfloat16* __restrict__ Oh, __nv_bfloat16* __restrict__ Ol)
{
    extern __shared__ char smem[];
    uint32_t sb = smem_u32(smem);
    const int qt = (int)gridDim.x - 1 - (int)blockIdx.x;   // LPT
    const int h  = blockIdx.y;
    const int b  = blockIdx.z;
    const int kvh = h / GROUPS;
    const int tid = threadIdx.x;
    const int lane = tid & 31;
    const int w = tid >> 5;
    const int qbase = qt * 128;

#pragma unroll
    for (int t = 0; t < 8; t++) {
        int i = tid + t * 128;
        int row = i >> 3;
        int c16 = i & 7;
        uint32_t doff = swz8(row, c16);
        size_t goff = (size_t)(b * SEQ + qbase + row) * DMODEL + h * HDIM + c16 * 8;
        CP_ASYNC16(sb + doff, Qh + goff);
        CP_ASYNC16(sb + 16384 + doff, Ql + goff);
    }
    size_t kvg0 = (size_t)(b * SEQ) * KVDIM + kvh * HDIM;
    stage_kv(Kh, Kl, Vh, Vl, sb + FQ_SMEM, kvg0, tid);
    CP_COMMIT();

    float acc[2][8][4];
#pragma unroll
    for (int mt = 0; mt < 2; mt++)
#pragma unroll
        for (int nt = 0; nt < 8; nt++)
#pragma unroll
            for (int e = 0; e < 4; e++) acc[mt][nt][e] = 0.f;
    float mrow[2][2] = {{-CUDART_INF_F, -CUDART_INF_F},
                        {-CUDART_INF_F, -CUDART_INF_F}};
    float lrow[2][2] = {{0.f, 0.f}, {0.f, 0.f}};

    const int nb = 2 * qt + 2;
    for (int c = 0; c < nb; c++) {
        if (c + 1 < nb) {
            stage_kv(Kh, Kl, Vh, Vl, sb + FQ_SMEM + ((c + 1) & 1) * KV_BUF,
                     kvg0 + (size_t)(c + 1) * 64 * KVDIM, tid);
            CP_COMMIT();
            CP_WAIT1();
        } else {
            CP_WAIT0();
        }
        __syncthreads();

        uint32_t sk = sb + FQ_SMEM + (c & 1) * KV_BUF;

        float S[2][8][4];
#pragma unroll
        for (int mt = 0; mt < 2; mt++)
#pragma unroll
            for (int nt = 0; nt < 8; nt++)
#pragma unroll
                for (int e = 0; e < 4; e++) S[mt][nt][e] = 0.f;

#pragma unroll
        for (int ks = 0; ks < 4; ks++) {
            uint32_t qh[2][4], ql[2][4];
#pragma unroll
            for (int mt = 0; mt < 2; mt++) {
                int row = w * 32 + mt * 16 + (lane & 15);
                int c16 = ks * 2 + (lane >> 4);
                uint32_t off = swz8(row, c16);
                LDMATRIX_X4(qh[mt][0], qh[mt][1], qh[mt][2], qh[mt][3], sb + off);
                LDMATRIX_X4(ql[mt][0], ql[mt][1], ql[mt][2], ql[mt][3],
                            sb + 16384 + off);
            }
#pragma unroll
            for (int np = 0; np < 4; np++) {
                int row = np * 16 + ((lane >> 4) * 8) + (lane & 7);
                int c16 = ks * 2 + ((lane >> 3) & 1);
                uint32_t off = swz8(row, c16);
                uint32_t kh[4], kl[4];
                LDMATRIX_X4(kh[0], kh[1], kh[2], kh[3], sk + off);
                LDMATRIX_X4(kl[0], kl[1], kl[2], kl[3], sk + 8192 + off);
#pragma unroll
                for (int mt = 0; mt < 2; mt++) {
                    MMA16816(S[mt][2 * np],     qh[mt], (kh + 0));
                    MMA16816(S[mt][2 * np + 1], qh[mt], (kh + 2));
                    MMA16816(S[mt][2 * np],     qh[mt], (kl + 0));
                    MMA16816(S[mt][2 * np + 1], qh[mt], (kl + 2));
                    MMA16816(S[mt][2 * np],     ql[mt], (kh + 0));
                    MMA16816(S[mt][2 * np + 1], ql[mt], (kh + 2));
                }
            }
        }

        if (c >= 2 * qt) {
            int kb = c * 64;
#pragma unroll
            for (int mt = 0; mt < 2; mt++) {
                int r0 = qbase + w * 32 + mt * 16 + (lane >> 2);
#pragma unroll
                for (int nt = 0; nt < 8; nt++) {
                    int key = kb + nt * 8 + (lane & 3) * 2;
                    if (key > r0)     S[mt][nt][0] = -CUDART_INF_F;
                    if (key + 1 > r0) S[mt][nt][1] = -CUDART_INF_F;
                    if (key > r0 + 8)     S[mt][nt][2] = -CUDART_INF_F;
                    if (key + 1 > r0 + 8) S[mt][nt][3] = -CUDART_INF_F;
                }
            }
        }

        uint32_t aPh[2][4][4], aPl[2][4][4];
#pragma unroll
        for (int mt = 0; mt < 2; mt++) {
#pragma unroll
            for (int e2 = 0; e2 < 2; e2++) {
                float mx = -CUDART_INF_F;
#pragma unroll
                for (int nt = 0; nt < 8; nt++)
                    mx = fmaxf(mx, fmaxf(S[mt][nt][2 * e2], S[mt][nt][2 * e2 + 1]));
                mx = fmaxf(mx, __shfl_xor_sync(0xffffffffu, mx, 1));
                mx = fmaxf(mx, __shfl_xor_sync(0xffffffffu, mx, 2));
                float mn = fmaxf(mrow[mt][e2], mx);
                float alpha = __expf(mrow[mt][e2] - mn);
                mrow[mt][e2] = mn;
                float sum = 0.f;
#pragma unroll
                for (int nt = 0; nt < 8; nt++) {
                    float p0 = __expf(S[mt][nt][2 * e2] - mn);
                    float p1 = __expf(S[mt][nt][2 * e2 + 1] - mn);
                    S[mt][nt][2 * e2] = p0;
                    S[mt][nt][2 * e2 + 1] = p1;
                    sum += p0 + p1;
                }
                sum += __shfl_xor_sync(0xffffffffu, sum, 1);
                sum += __shfl_xor_sync(0xffffffffu, sum, 2);
                lrow[mt][e2] = lrow[mt][e2] * alpha + sum;
#pragma unroll
                for (int nt = 0; nt < 8; nt++) {
                    acc[mt][nt][2 * e2] *= alpha;
                    acc[mt][nt][2 * e2 + 1] *= alpha;
                }
            }
#pragma unroll
            for (int kc = 0; kc < 4; kc++) {
#pragma unroll
                for (int r = 0; r < 4; r++) {
                    int nt = 2 * kc + (r >> 1);
                    int e0 = (r & 1) * 2;
                    float p0 = S[mt][nt][e0], p1 = S[mt][nt][e0 + 1];
                    __nv_bfloat162 hh = __floats2bfloat162_rn(p0, p1);
                    float r0 = p0 - __bfloat162float(hh.x);
                    float r1 = p1 - __bfloat162float(hh.y);
                    __nv_bfloat162 ll = __floats2bfloat162_rn(r0, r1);
                    aPh[mt][kc][r] = *reinterpret_cast<uint32_t*>(&hh);
                    aPl[mt][kc][r] = *reinterpret_cast<uint32_t*>(&ll);
                }
            }
        }

#pragma unroll
        for (int kc = 0; kc < 4; kc++) {
#pragma unroll
            for (int dp = 0; dp < 4; dp++) {
                int row = kc * 16 + ((lane >> 3) & 1) * 8 + (lane & 7);
                int c16 = dp * 2 + (lane >> 4);
                uint32_t off = swz8(row, c16);
                uint32_t vh[4], vl[4];
                LDMATRIX_X4T(vh[0], vh[1], vh[2], vh[3], sk + 16384 + off);
                LDMATRIX_X4T(vl[0], vl[1], vl[2], vl[3], sk + 24576 + off);
#pragma unroll
                for (int mt = 0; mt < 2; mt++) {
                    MMA16816(acc[mt][2 * dp],     aPh[mt][kc], (vh + 0));
                    MMA16816(acc[mt][2 * dp + 1], aPh[mt][kc], (vh + 2));
                    MMA16816(acc[mt][2 * dp],     aPh[mt][kc], (vl + 0));
                    MMA16816(acc[mt][2 * dp + 1], aPh[mt][kc], (vl + 2));
                    MMA16816(acc[mt][2 * dp],     aPl[mt][kc], (vh + 0));
                    MMA16816(acc[mt][2 * dp + 1], aPl[mt][kc], (vh + 2));
                }
            }
        }
        __syncthreads();
    }

#pragma unroll
    for (int mt = 0; mt < 2; mt++) {
        float inv0 = 1.0f / lrow[mt][0];
        float inv1 = 1.0f / lrow[mt][1];
        int r0 = qbase + w * 32 + mt * 16 + (lane >> 2);
        size_t t0 = (size_t)(b * SEQ + r0) * DMODEL + h * HDIM;
        size_t t1 = t0 + 8 * DMODEL;
#pragma unroll
        for (int nt = 0; nt < 8; nt++) {
            int d = nt * 8 + (lane & 3) * 2;
            float v0 = acc[mt][nt][0] * inv0, v1 = acc[mt][nt][1] * inv0;
            float v2 = acc[mt][nt][2] * inv1, v3 = acc[mt][nt][3] * inv1;
            __nv_bfloat162 h01 = __floats2bfloat162_rn(v0, v1);
            __nv_bfloat162 h23 = __floats2bfloat162_rn(v2, v3);
            __nv_bfloat162 l01 = __floats2bfloat162_rn(
                v0 - __bfloat162float(h01.x), v1 - __bfloat162float(h01.y));
            __nv_bfloat162 l23 = __floats2bfloat162_rn(
                v2 - __bfloat162float(h23.x), v3 - __bfloat162float(h23.y));
            *reinterpret_cast<__nv_bfloat162*>(Oh + t0 + d) = h01;
            *reinterpret_cast<__nv_bfloat162*>(Oh + t1 + d) = h23;
            *reinterpret_cast<__nv_bfloat162*>(Ol + t0 + d) = l01;
            *reinterpret_cast<__nv_bfloat162*>(Ol + t1 + d) = l23;
        }
    }
}

// ---------------- launch ----------------------------------------------------
extern "C" void kernel_launch(void* const* d_in, const int* in_sizes, int n_in,
                              void* d_out, int out_size)
{
    const float* hidden = (const float*)d_in[0];
    const float* cs     = (const float*)d_in[1];
    const float* sn     = (const float*)d_in[2];
    const float* Wq     = (const float*)d_in[3];
    const float* Wk     = (const float*)d_in[4];
    const float* Wv     = (const float*)d_in[5];
    const float* Wo     = (const float*)d_in[6];
    float* out          = (float*)d_out;

    float* QKV = nullptr; cudaGetSymbolAddress((void**)&QKV, g_QKV);
    __nv_bfloat16* Ah = nullptr; cudaGetSymbolAddress((void**)&Ah, g_Ahi);
    __nv_bfloat16* Al = nullptr; cudaGetSymbolAddress((void**)&Al, g_Alo);
    __nv_bfloat16* Bh = nullptr; cudaGetSymbolAddress((void**)&Bh, g_Bhi);
    __nv_bfloat16* Bl = nullptr; cudaGetSymbolAddress((void**)&Bl, g_Blo);
    __nv_bfloat16* Qh = nullptr; cudaGetSymbolAddress((void**)&Qh, g_Qh);
    __nv_bfloat16* Ql = nullptr; cudaGetSymbolAddress((void**)&Ql, g_Ql);
    __nv_bfloat16* Kh = nullptr; cudaGetSymbolAddress((void**)&Kh, g_Kh);
    __nv_bfloat16* Kl = nullptr; cudaGetSymbolAddress((void**)&Kl, g_Kl);
    __nv_bfloat16* Vh = nullptr; cudaGetSymbolAddress((void**)&Vh, g_Vh);
    __nv_bfloat16* Vl = nullptr; cudaGetSymbolAddress((void**)&Vl, g_Vl);

    static bool attr_set = false;
    if (!attr_set) {
        cudaFuncSetAttribute(gemm_mma, cudaFuncAttributeMaxDynamicSharedMemorySize,
                             GEMM_SMEM);
        cudaFuncSetAttribute(flash_mma, cudaFuncAttributeMaxDynamicSharedMemorySize,
                             FLASH_SMEM);
        attr_set = true;
    }

    // merged prep: hidden split + Wq/Wk/Wv transpose, ONE launch
    prep_kernel<<<PREP_BLOCKS, 256>>>(hidden, (__nv_bfloat162*)Ah,
                                      (__nv_bfloat162*)Al, Wq, Wk, Wv, Bh, Bl);

    // fused QKV GEMM
    gemm_mma<<<dim3(QKVN / BN, TOK / BM), 256, GEMM_SMEM>>>(Ah, Al, Bh, Bl, QKV, QKVN);

    // merged post: Q rope + K rope + V split + Wo transpose, ONE launch
    post_kernel<<<POST_BLOCKS, 256>>>(QKV, cs, sn, Qh, Ql, Kh, Kl,
                                      (__nv_bfloat162*)Vh, (__nv_bfloat162*)Vl,
                                      Wo, Bh, Bl);

    // flash attention (LPT) -> writes bf16 hi/lo into Wo-GEMM A buffers
    {
        dim3 grid(SEQ / 128, NHEADS, BSZ);
        flash_mma<<<grid, 128, FLASH_SMEM>>>(Qh, Ql, Kh, Kl, Vh, Vl, Ah, Al);
    }

    // out = attn @ Wo
    gemm_mma<<<dim3(DMODEL / BN, TOK / BM), 256, GEMM_SMEM>>>(Ah, Al, Bh, Bl, out, DMODEL);
}